// round 3
// baseline (speedup 1.0000x reference)
#include <cuda_runtime.h>
#include <cuda_fp16.h>

#define NN 100000      // nodes
#define DD 64          // feature dim
#define EE 800000      // edges
#define LLAYERS 2

// ---------------------------------------------------------------------------
// Scratch (device globals; no allocation anywhere)
// ---------------------------------------------------------------------------
__device__ float  d_eb[3][2][NN * DD];   // fp32 canonical state [branch][buf]
__device__ float  d_P[NN * DD];          // e1 @ W1_top + b1 (fp32, read at self)
__device__ __half d_Qh[NN * DD];         // e1 @ W1_bot (gather-only -> fp16)
__device__ __half d_gatedh[NN * DD];     // gate * e2   (gather-only -> fp16)
__device__ __half d_e0h[2][NN * DD];     // fp16 gather mirrors, double buffered
__device__ __half d_e1h[2][NN * DD];
__device__ int    d_deg[NN];
__device__ int    d_rowptr[NN];
__device__ int    d_cursor[NN];
__device__ int    d_csr_t[EE];
__device__ float  d_csr_g[EE];
__device__ int    d_csr_eid[EE];

__device__ __forceinline__ float sigmoidf(float x) {
    return 1.0f / (1.0f + expf(-x));
}

// ---- packed f32x2 helpers (Blackwell) -------------------------------------
__device__ __forceinline__ unsigned long long pack2(float x, float y) {
    unsigned long long r;
    asm("mov.b64 %0,{%1,%2};" : "=l"(r) : "f"(x), "f"(y));
    return r;
}
__device__ __forceinline__ float2 unpack2(unsigned long long v) {
    float2 r;
    asm("mov.b64 {%0,%1},%2;" : "=f"(r.x), "=f"(r.y) : "l"(v));
    return r;
}
__device__ __forceinline__ void fma2(unsigned long long& d,
                                     unsigned long long a, unsigned long long b) {
    asm("fma.rn.f32x2 %0, %1, %2, %0;" : "+l"(d) : "l"(a), "l"(b));
}

// ---- fp16 quad load/store --------------------------------------------------
__device__ __forceinline__ float4 ld_h4(const __half* p) {
    uint2 r = *(const uint2*)p;
    __half2 h0 = *reinterpret_cast<__half2*>(&r.x);
    __half2 h1 = *reinterpret_cast<__half2*>(&r.y);
    float2 f0 = __half22float2(h0);
    float2 f1 = __half22float2(h1);
    return make_float4(f0.x, f0.y, f1.x, f1.y);
}
__device__ __forceinline__ void st_h4(__half* p, float4 v) {
    __half2 h0 = __floats2half2_rn(v.x, v.y);
    __half2 h1 = __floats2half2_rn(v.z, v.w);
    uint2 r;
    r.x = *reinterpret_cast<unsigned*>(&h0);
    r.y = *reinterpret_cast<unsigned*>(&h1);
    *(uint2*)p = r;
}

// ---------------------------------------------------------------------------
// CSR build
// ---------------------------------------------------------------------------
__global__ void k_zero_deg() {
    int n = blockIdx.x * blockDim.x + threadIdx.x;
    if (n < NN) d_deg[n] = 0;
}

__global__ void k_count(const int* __restrict__ h_idx) {
    int e = blockIdx.x * blockDim.x + threadIdx.x;
    if (e < EE) atomicAdd(&d_deg[h_idx[e]], 1);
}

__global__ void k_scan() {
    __shared__ int s[1024];
    int t = threadIdx.x;
    const int C = (NN + 1023) / 1024;
    int base = t * C;
    int sum = 0;
    for (int i = 0; i < C; i++) {
        int n = base + i;
        if (n < NN) sum += d_deg[n];
    }
    s[t] = sum;
    __syncthreads();
    for (int off = 1; off < 1024; off <<= 1) {
        int v = (t >= off) ? s[t - off] : 0;
        __syncthreads();
        s[t] += v;
        __syncthreads();
    }
    int run = s[t] - sum;  // exclusive prefix
    for (int i = 0; i < C; i++) {
        int n = base + i;
        if (n < NN) {
            d_rowptr[n] = run;
            d_cursor[n] = run;
            run += d_deg[n];
        }
    }
}

__global__ void k_fill(const int* __restrict__ h_idx, const int* __restrict__ t_idx,
                       const float* __restrict__ G) {
    int e = blockIdx.x * blockDim.x + threadIdx.x;
    if (e >= EE) return;
    int h = h_idx[e];
    int pos = atomicAdd(&d_cursor[h], 1);
    d_csr_t[pos] = t_idx[e];
    d_csr_g[pos] = G[e];
    d_csr_eid[pos] = e;
}

// k_prep: fp16 mirrors of emb0 (layer-0 gather sources)
__global__ void k_prep(const float4* __restrict__ emb0) {
    int i = blockIdx.x * blockDim.x + threadIdx.x;
    if (i >= NN * DD / 4) return;
    float4 v = emb0[i];
    st_h4(&d_e0h[0][i * 4], v);
    st_h4(&d_e1h[0][i * 4], v);
}

// ---------------------------------------------------------------------------
// K_node_pq: P = e1 @ W1_top + b1 (fp32) ; Qh = e1 @ W1_bot (fp16)
// 4 nodes / warp; lane owns cols (2*lane, 2*lane+1); f32x2 FMAs.
// ---------------------------------------------------------------------------
__global__ __launch_bounds__(256) void k_node_pq(
    const float* __restrict__ e1c,
    const float* __restrict__ W1,   // [128,64] (top rows 0..63, bot 64..127)
    const float* __restrict__ b1)   // [64]
{
    __shared__ float sW[128 * 64];
    __shared__ float sB1[64];

    int tid = threadIdx.x;
    for (int i = tid; i < 128 * 64 / 4; i += blockDim.x)
        ((float4*)sW)[i] = ((const float4*)W1)[i];
    if (tid < 64) sB1[tid] = b1[tid];
    __syncthreads();

    int gwarp = (blockIdx.x * blockDim.x + tid) >> 5;
    int lane = tid & 31;
    int j = lane * 2;
    int n0 = gwarp * 4;  // 3125 blocks * 8 warps * 4 = 100000 exactly

    float a[4], b[4];
    unsigned long long p[4], q[4];
    unsigned long long binit = *(const unsigned long long*)&sB1[j];
#pragma unroll
    for (int m = 0; m < 4; m++) {
        a[m] = e1c[(n0 + m) * 64 + lane];
        b[m] = e1c[(n0 + m) * 64 + 32 + lane];
        p[m] = binit;
        q[m] = pack2(0.0f, 0.0f);
    }
#pragma unroll
    for (int k = 0; k < 64; k++) {
        unsigned long long wt = *(const unsigned long long*)&sW[k * 64 + j];
        unsigned long long wb = *(const unsigned long long*)&sW[4096 + k * 64 + j];
#pragma unroll
        for (int m = 0; m < 4; m++) {
            float v = __shfl_sync(0xffffffffu, (k < 32) ? a[m] : b[m], k & 31);
            unsigned long long vv = pack2(v, v);
            fma2(p[m], vv, wt);
            fma2(q[m], vv, wb);
        }
    }
#pragma unroll
    for (int m = 0; m < 4; m++) {
        float2 pf = unpack2(p[m]);
        float2 qf = unpack2(q[m]);
        *(float2*)&d_P[(n0 + m) * 64 + j] = pf;
        __half2 qh = __floats2half2_rn(qf.x, qf.y);
        *(__half2*)&d_Qh[(n0 + m) * 64 + j] = qh;
    }
}

// ---------------------------------------------------------------------------
// K_node_gate: gatedh = sigmoid(gum + relu(e2@W1+b1)@W2 + b2) * e2   (fp16)
// 4 nodes / warp; f32x2 FMAs.
// ---------------------------------------------------------------------------
__global__ __launch_bounds__(256) void k_node_gate(
    const float* __restrict__ e2c,
    const float* __restrict__ W1,   // [64,64]
    const float* __restrict__ b1,   // [64]
    const float* __restrict__ W2,   // [64,64]
    const float* __restrict__ b2,   // [64]
    const float* __restrict__ gum)  // [N,64] layer slice
{
    __shared__ float sW1[64 * 64];
    __shared__ float sW2[64 * 64];
    __shared__ float sB1[64], sB2[64];

    int tid = threadIdx.x;
    for (int i = tid; i < 64 * 64 / 4; i += blockDim.x) {
        ((float4*)sW1)[i] = ((const float4*)W1)[i];
        ((float4*)sW2)[i] = ((const float4*)W2)[i];
    }
    if (tid < 64) { sB1[tid] = b1[tid]; sB2[tid] = b2[tid]; }
    __syncthreads();

    int gwarp = (blockIdx.x * blockDim.x + tid) >> 5;
    int lane = tid & 31;
    int j = lane * 2;
    int n0 = gwarp * 4;

    float a[4], b[4];
    unsigned long long hacc[4];
    unsigned long long b1init = *(const unsigned long long*)&sB1[j];
#pragma unroll
    for (int m = 0; m < 4; m++) {
        a[m] = e2c[(n0 + m) * 64 + lane];
        b[m] = e2c[(n0 + m) * 64 + 32 + lane];
        hacc[m] = b1init;
    }
#pragma unroll
    for (int k = 0; k < 64; k++) {
        unsigned long long w1 = *(const unsigned long long*)&sW1[k * 64 + j];
#pragma unroll
        for (int m = 0; m < 4; m++) {
            float v = __shfl_sync(0xffffffffu, (k < 32) ? a[m] : b[m], k & 31);
            fma2(hacc[m], pack2(v, v), w1);
        }
    }
    float2 h[4];
    unsigned long long lg[4];
    unsigned long long b2init = *(const unsigned long long*)&sB2[j];
#pragma unroll
    for (int m = 0; m < 4; m++) {
        float2 hf = unpack2(hacc[m]);
        h[m] = make_float2(fmaxf(hf.x, 0.0f), fmaxf(hf.y, 0.0f));
        lg[m] = b2init;
    }
#pragma unroll
    for (int k = 0; k < 64; k++) {
        unsigned long long w2 = *(const unsigned long long*)&sW2[k * 64 + j];
#pragma unroll
        for (int m = 0; m < 4; m++) {
            float hv = __shfl_sync(0xffffffffu, (k & 1) ? h[m].y : h[m].x, k >> 1);
            fma2(lg[m], pack2(hv, hv), w2);
        }
    }
#pragma unroll
    for (int m = 0; m < 4; m++) {
        int n = n0 + m;
        float2 lgf = unpack2(lg[m]);
        float2 gmv = *(const float2*)&gum[n * 64 + j];
        float2 x2 = *(const float2*)&e2c[n * 64 + j];
        float gx = sigmoidf(gmv.x + lgf.x);
        float gy = sigmoidf(gmv.y + lgf.y);
        __half2 o = __floats2half2_rn(gx * x2.x, gy * x2.y);
        *(__half2*)&d_gatedh[n * 64 + j] = o;
    }
}

// ---------------------------------------------------------------------------
// K_layer_edge: fused per-node edge weights + row norm + 3-branch SpMM + residual.
// 16 threads per node; gathers from fp16 mirrors; fp32 accumulate + residual.
// ---------------------------------------------------------------------------
__global__ __launch_bounds__(256) void k_layer_edge(
    const float* __restrict__ e0c, const float* __restrict__ e1c,
    const float* __restrict__ e2c,
    const __half* __restrict__ e0h, const __half* __restrict__ e1h,
    float* __restrict__ e0n, float* __restrict__ e1n, float* __restrict__ e2n,
    __half* __restrict__ e0nh, __half* __restrict__ e1nh, int write_h,
    const float* __restrict__ W2,   // [64] layer slice
    const float* __restrict__ b2p,  // scalar
    const float* __restrict__ gum)  // [E] layer slice
{
    __shared__ float sW2[64];
    if (threadIdx.x < 64) sW2[threadIdx.x] = W2[threadIdx.x];
    __syncthreads();

    int node = blockIdx.x * 16 + (threadIdx.x >> 4);  // 6250 * 16 = 100000
    int sub = threadIdx.x & 15;
    int j = sub * 4;

    int start = d_rowptr[node];
    int deg = d_deg[node];
    float b2 = __ldg(b2p);

    float4 p = *(const float4*)&d_P[node * 64 + j];
    float4 wv = *(const float4*)&sW2[j];

    float rowsum = 0.0f;
    float4 a0 = make_float4(0.f, 0.f, 0.f, 0.f);
    float4 a1 = a0, a2 = a0;

    for (int it = 0; it < deg; it++) {
        int pos = start + it;
        int t = d_csr_t[pos];
        int eid = d_csr_eid[pos];
        float g = d_csr_g[pos];

        float4 q = ld_h4(&d_Qh[t * 64 + j]);
        float rx = fmaxf(p.x + q.x, 0.0f);
        float ry = fmaxf(p.y + q.y, 0.0f);
        float rz = fmaxf(p.z + q.z, 0.0f);
        float rw = fmaxf(p.w + q.w, 0.0f);
        float dot = rx * wv.x + ry * wv.y + rz * wv.z + rw * wv.w;
#pragma unroll
        for (int off = 8; off >= 1; off >>= 1)
            dot += __shfl_xor_sync(0xffffffffu, dot, off, 16);

        float w = sigmoidf(gum[eid] + dot + b2);
        rowsum += w;

        float4 f0 = ld_h4(&e0h[t * 64 + j]);
        a0.x = fmaf(g, f0.x, a0.x); a0.y = fmaf(g, f0.y, a0.y);
        a0.z = fmaf(g, f0.z, a0.z); a0.w = fmaf(g, f0.w, a0.w);
        float4 f1 = ld_h4(&e1h[t * 64 + j]);
        a1.x = fmaf(w, f1.x, a1.x); a1.y = fmaf(w, f1.y, a1.y);
        a1.z = fmaf(w, f1.z, a1.z); a1.w = fmaf(w, f1.w, a1.w);
        float4 f2 = ld_h4(&d_gatedh[t * 64 + j]);
        a2.x = fmaf(g, f2.x, a2.x); a2.y = fmaf(g, f2.y, a2.y);
        a2.z = fmaf(g, f2.z, a2.z); a2.w = fmaf(g, f2.w, a2.w);
    }

    float dinv = (rowsum > 0.0f) ? (1.0f / rowsum) : 0.0f;

    float4 c0 = *(const float4*)&e0c[node * 64 + j];
    float4 c1 = *(const float4*)&e1c[node * 64 + j];
    float4 c2 = *(const float4*)&e2c[node * 64 + j];

    float4 o0 = make_float4(c0.x + a0.x, c0.y + a0.y, c0.z + a0.z, c0.w + a0.w);
    float4 o1 = make_float4(fmaf(dinv, a1.x, c1.x), fmaf(dinv, a1.y, c1.y),
                            fmaf(dinv, a1.z, c1.z), fmaf(dinv, a1.w, c1.w));
    float4 o2 = make_float4(c2.x + a2.x, c2.y + a2.y, c2.z + a2.z, c2.w + a2.w);

    *(float4*)&e0n[node * 64 + j] = o0;
    *(float4*)&e1n[node * 64 + j] = o1;
    *(float4*)&e2n[node * 64 + j] = o2;
    if (write_h) {
        st_h4(&e0nh[node * 64 + j], o0);
        st_h4(&e1nh[node * 64 + j], o1);
    }
}

// ---------------------------------------------------------------------------
// K_finish: out[b] = emb0 + e_layer1[b] + e_layer2[b]
// ---------------------------------------------------------------------------
__global__ void k_finish(const float4* __restrict__ emb0, float4* __restrict__ out) {
    int i = blockIdx.x * blockDim.x + threadIdx.x;
    const int per = NN * (DD / 4);
    if (i >= per) return;
    float4 e = emb0[i];
#pragma unroll
    for (int b = 0; b < 3; b++) {
        float4 v1 = ((const float4*)d_eb[b][0])[i];
        float4 v2 = ((const float4*)d_eb[b][1])[i];
        out[b * per + i] = make_float4(e.x + v1.x + v2.x, e.y + v1.y + v2.y,
                                       e.z + v1.z + v2.z, e.w + v1.w + v2.w);
    }
}

// ---------------------------------------------------------------------------
// Host launcher (graph-capturable: launches only)
// ---------------------------------------------------------------------------
extern "C" void kernel_launch(void* const* d_in, const int* in_sizes, int n_in,
                              void* d_out, int out_size) {
    const float* emb0 = (const float*)d_in[0];
    const int*   hI   = (const int*)  d_in[1];
    const int*   tI   = (const int*)  d_in[2];
    const float* G    = (const float*)d_in[3];
    const float* egum = (const float*)d_in[4];   // [L,E]
    const float* ngum = (const float*)d_in[5];   // [L,N,D]
    const float* eW1  = (const float*)d_in[6];   // [L,128,64]
    const float* eb1  = (const float*)d_in[7];   // [L,64]
    const float* eW2  = (const float*)d_in[8];   // [L,64,1]
    const float* eb2  = (const float*)d_in[9];   // [L,1]
    const float* mW1  = (const float*)d_in[10];  // [L,64,64]
    const float* mb1  = (const float*)d_in[11];  // [L,64]
    const float* mW2  = (const float*)d_in[12];  // [L,64,64]
    const float* mb2  = (const float*)d_in[13];  // [L,64]
    float* out = (float*)d_out;

    // CSR build (once per launch)
    k_zero_deg<<<(NN + 255) / 256, 256>>>();
    k_count<<<(EE + 255) / 256, 256>>>(hI);
    k_scan<<<1, 1024>>>();
    k_fill<<<(EE + 255) / 256, 256>>>(hI, tI, G);
    k_prep<<<(NN * DD / 4 + 255) / 256, 256>>>((const float4*)emb0);

    float* base;
    cudaGetSymbolAddress((void**)&base, d_eb);
    __half* h0base;
    cudaGetSymbolAddress((void**)&h0base, d_e0h);
    __half* h1base;
    cudaGetSymbolAddress((void**)&h1base, d_e1h);

    float* ebuf[3][2];
    for (int b = 0; b < 3; b++)
        for (int s = 0; s < 2; s++)
            ebuf[b][s] = base + ((size_t)b * 2 + s) * (size_t)NN * DD;
    __half* e0hbuf[2] = { h0base, h0base + (size_t)NN * DD };
    __half* e1hbuf[2] = { h1base, h1base + (size_t)NN * DD };

    for (int i = 0; i < LLAYERS; i++) {
        const float* c0 = (i == 0) ? emb0 : ebuf[0][(i - 1) & 1];
        const float* c1 = (i == 0) ? emb0 : ebuf[1][(i - 1) & 1];
        const float* c2 = (i == 0) ? emb0 : ebuf[2][(i - 1) & 1];
        float* n0 = ebuf[0][i & 1];
        float* n1 = ebuf[1][i & 1];
        float* n2 = ebuf[2][i & 1];
        const __half* h0in = e0hbuf[i & 1];       // layer0 reads buf0 (prep)
        const __half* h1in = e1hbuf[i & 1];
        __half* h0out = e0hbuf[(i & 1) ^ 1];
        __half* h1out = e1hbuf[(i & 1) ^ 1];
        int write_h = (i + 1 < LLAYERS) ? 1 : 0;

        k_node_pq<<<3125, 256>>>(c1, eW1 + i * 128 * 64, eb1 + i * 64);
        k_node_gate<<<3125, 256>>>(c2, mW1 + i * 64 * 64, mb1 + i * 64,
                                   mW2 + i * 64 * 64, mb2 + i * 64,
                                   ngum + (size_t)i * NN * 64);
        k_layer_edge<<<6250, 256>>>(c0, c1, c2, h0in, h1in,
                                    n0, n1, n2, h0out, h1out, write_h,
                                    eW2 + i * 64, eb2 + i,
                                    egum + (size_t)i * EE);
    }

    k_finish<<<(NN * DD / 4 + 255) / 256, 256>>>((const float4*)emb0, (float4*)out);
}

// round 4
// speedup vs baseline: 1.1563x; 1.1563x over previous
#include <cuda_runtime.h>
#include <cuda_fp16.h>

#define NN 100000      // nodes
#define DD 64          // feature dim
#define EE 800000      // edges
#define LLAYERS 2

// ---------------------------------------------------------------------------
// Scratch (device globals; no allocation anywhere)
// ---------------------------------------------------------------------------
__device__ float  d_eb[3][2][NN * DD];   // fp32 canonical state [branch][buf]
__device__ __half d_Ph[NN * DD];         // e1 @ W1_top + b1  (fp16)
__device__ __half d_Qh[NN * DD];         // e1 @ W1_bot       (fp16)
__device__ __half d_gatedh[NN * DD];     // gate * e2         (fp16)
__device__ __half d_e0h[2][NN * DD];     // fp16 gather mirrors, double buffered
__device__ __half d_e1h[2][NN * DD];
__device__ int    d_deg[NN];
__device__ int    d_rowptr[NN];
__device__ int    d_cursor[NN];
__device__ int    d_csr_h[EE];
__device__ int    d_csr_t[EE];
__device__ float  d_csr_g[EE];
__device__ float  d_csr_gum[LLAYERS][EE];  // gumbel + b2, CSR order
__device__ float  d_wcsr[EE];              // edge weights, CSR order

__device__ __forceinline__ float fsig(float x) {
    return __fdividef(1.0f, 1.0f + __expf(-x));
}

// ---- packed f32x2 helpers (Blackwell) -------------------------------------
__device__ __forceinline__ unsigned long long pack2(float x, float y) {
    unsigned long long r;
    asm("mov.b64 %0,{%1,%2};" : "=l"(r) : "f"(x), "f"(y));
    return r;
}
__device__ __forceinline__ float2 unpack2(unsigned long long v) {
    float2 r;
    asm("mov.b64 {%0,%1},%2;" : "=f"(r.x), "=f"(r.y) : "l"(v));
    return r;
}
__device__ __forceinline__ void fma2(unsigned long long& d,
                                     unsigned long long a, unsigned long long b) {
    asm("fma.rn.f32x2 %0, %1, %2, %0;" : "+l"(d) : "l"(a), "l"(b));
}

// ---- fp16 quad/oct load, quad store ---------------------------------------
__device__ __forceinline__ float4 ld_h4(const __half* p) {
    uint2 r = *(const uint2*)p;
    __half2 h0 = *reinterpret_cast<__half2*>(&r.x);
    __half2 h1 = *reinterpret_cast<__half2*>(&r.y);
    float2 f0 = __half22float2(h0);
    float2 f1 = __half22float2(h1);
    return make_float4(f0.x, f0.y, f1.x, f1.y);
}
__device__ __forceinline__ void ld_h8(const __half* p, float* f) {
    uint4 r = *(const uint4*)p;
    float2 a = __half22float2(*reinterpret_cast<__half2*>(&r.x));
    float2 b = __half22float2(*reinterpret_cast<__half2*>(&r.y));
    float2 c = __half22float2(*reinterpret_cast<__half2*>(&r.z));
    float2 d = __half22float2(*reinterpret_cast<__half2*>(&r.w));
    f[0] = a.x; f[1] = a.y; f[2] = b.x; f[3] = b.y;
    f[4] = c.x; f[5] = c.y; f[6] = d.x; f[7] = d.y;
}
__device__ __forceinline__ void st_h4(__half* p, float4 v) {
    __half2 h0 = __floats2half2_rn(v.x, v.y);
    __half2 h1 = __floats2half2_rn(v.z, v.w);
    uint2 r;
    r.x = *reinterpret_cast<unsigned*>(&h0);
    r.y = *reinterpret_cast<unsigned*>(&h1);
    *(uint2*)p = r;
}

// ---------------------------------------------------------------------------
// CSR build
// ---------------------------------------------------------------------------
__global__ void k_zero_deg() {
    int n = blockIdx.x * blockDim.x + threadIdx.x;
    if (n < NN) d_deg[n] = 0;
}

__global__ void k_count(const int* __restrict__ h_idx) {
    int e = blockIdx.x * blockDim.x + threadIdx.x;
    if (e < EE) atomicAdd(&d_deg[h_idx[e]], 1);
}

__global__ void k_scan() {
    __shared__ int s[1024];
    int t = threadIdx.x;
    const int C = (NN + 1023) / 1024;
    int base = t * C;
    int sum = 0;
    for (int i = 0; i < C; i++) {
        int n = base + i;
        if (n < NN) sum += d_deg[n];
    }
    s[t] = sum;
    __syncthreads();
    for (int off = 1; off < 1024; off <<= 1) {
        int v = (t >= off) ? s[t - off] : 0;
        __syncthreads();
        s[t] += v;
        __syncthreads();
    }
    int run = s[t] - sum;  // exclusive prefix
    for (int i = 0; i < C; i++) {
        int n = base + i;
        if (n < NN) {
            d_rowptr[n] = run;
            d_cursor[n] = run;
            run += d_deg[n];
        }
    }
}

__global__ void k_fill(const int* __restrict__ h_idx, const int* __restrict__ t_idx,
                       const float* __restrict__ G,
                       const float* __restrict__ egum,  // [L,E]
                       const float* __restrict__ eb2)   // [L]
{
    int e = blockIdx.x * blockDim.x + threadIdx.x;
    if (e >= EE) return;
    int h = h_idx[e];
    int pos = atomicAdd(&d_cursor[h], 1);
    d_csr_h[pos] = h;
    d_csr_t[pos] = t_idx[e];
    d_csr_g[pos] = G[e];
    d_csr_gum[0][pos] = egum[e] + __ldg(&eb2[0]);
    d_csr_gum[1][pos] = egum[EE + e] + __ldg(&eb2[1]);
}

// k_prep: fp16 mirrors of emb0 (layer-0 gather sources)
__global__ void k_prep(const float4* __restrict__ emb0) {
    int i = blockIdx.x * blockDim.x + threadIdx.x;
    if (i >= NN * DD / 4) return;
    float4 v = emb0[i];
    st_h4(&d_e0h[0][i * 4], v);
    st_h4(&d_e1h[0][i * 4], v);
}

// ---------------------------------------------------------------------------
// K_node_pq: Ph = e1 @ W1_top + b1 ; Qh = e1 @ W1_bot   (both fp16)
// 4 nodes / warp; lane owns cols (2*lane, 2*lane+1); f32x2 FMAs.
// ---------------------------------------------------------------------------
__global__ __launch_bounds__(256) void k_node_pq(
    const float* __restrict__ e1c,
    const float* __restrict__ W1,   // [128,64] (top rows 0..63, bot 64..127)
    const float* __restrict__ b1)   // [64]
{
    __shared__ float sW[128 * 64];
    __shared__ float sB1[64];

    int tid = threadIdx.x;
    for (int i = tid; i < 128 * 64 / 4; i += blockDim.x)
        ((float4*)sW)[i] = ((const float4*)W1)[i];
    if (tid < 64) sB1[tid] = b1[tid];
    __syncthreads();

    int gwarp = (blockIdx.x * blockDim.x + tid) >> 5;
    int lane = tid & 31;
    int j = lane * 2;
    int n0 = gwarp * 4;  // 3125 blocks * 8 warps * 4 = 100000 exactly

    float a[4], b[4];
    unsigned long long p[4], q[4];
    unsigned long long binit = *(const unsigned long long*)&sB1[j];
#pragma unroll
    for (int m = 0; m < 4; m++) {
        a[m] = e1c[(n0 + m) * 64 + lane];
        b[m] = e1c[(n0 + m) * 64 + 32 + lane];
        p[m] = binit;
        q[m] = pack2(0.0f, 0.0f);
    }
#pragma unroll
    for (int k = 0; k < 64; k++) {
        unsigned long long wt = *(const unsigned long long*)&sW[k * 64 + j];
        unsigned long long wb = *(const unsigned long long*)&sW[4096 + k * 64 + j];
#pragma unroll
        for (int m = 0; m < 4; m++) {
            float v = __shfl_sync(0xffffffffu, (k < 32) ? a[m] : b[m], k & 31);
            unsigned long long vv = pack2(v, v);
            fma2(p[m], vv, wt);
            fma2(q[m], vv, wb);
        }
    }
#pragma unroll
    for (int m = 0; m < 4; m++) {
        float2 pf = unpack2(p[m]);
        float2 qf = unpack2(q[m]);
        *(__half2*)&d_Ph[(n0 + m) * 64 + j] = __floats2half2_rn(pf.x, pf.y);
        *(__half2*)&d_Qh[(n0 + m) * 64 + j] = __floats2half2_rn(qf.x, qf.y);
    }
}

// ---------------------------------------------------------------------------
// K_node_gate: gatedh = sigmoid(gum + relu(e2@W1+b1)@W2 + b2) * e2   (fp16)
// ---------------------------------------------------------------------------
__global__ __launch_bounds__(256) void k_node_gate(
    const float* __restrict__ e2c,
    const float* __restrict__ W1,   // [64,64]
    const float* __restrict__ b1,   // [64]
    const float* __restrict__ W2,   // [64,64]
    const float* __restrict__ b2,   // [64]
    const float* __restrict__ gum)  // [N,64] layer slice
{
    __shared__ float sW1[64 * 64];
    __shared__ float sW2[64 * 64];
    __shared__ float sB1[64], sB2[64];

    int tid = threadIdx.x;
    for (int i = tid; i < 64 * 64 / 4; i += blockDim.x) {
        ((float4*)sW1)[i] = ((const float4*)W1)[i];
        ((float4*)sW2)[i] = ((const float4*)W2)[i];
    }
    if (tid < 64) { sB1[tid] = b1[tid]; sB2[tid] = b2[tid]; }
    __syncthreads();

    int gwarp = (blockIdx.x * blockDim.x + tid) >> 5;
    int lane = tid & 31;
    int j = lane * 2;
    int n0 = gwarp * 4;

    float a[4], b[4];
    unsigned long long hacc[4];
    unsigned long long b1init = *(const unsigned long long*)&sB1[j];
#pragma unroll
    for (int m = 0; m < 4; m++) {
        a[m] = e2c[(n0 + m) * 64 + lane];
        b[m] = e2c[(n0 + m) * 64 + 32 + lane];
        hacc[m] = b1init;
    }
#pragma unroll
    for (int k = 0; k < 64; k++) {
        unsigned long long w1 = *(const unsigned long long*)&sW1[k * 64 + j];
#pragma unroll
        for (int m = 0; m < 4; m++) {
            float v = __shfl_sync(0xffffffffu, (k < 32) ? a[m] : b[m], k & 31);
            fma2(hacc[m], pack2(v, v), w1);
        }
    }
    float2 h[4];
    unsigned long long lg[4];
    unsigned long long b2init = *(const unsigned long long*)&sB2[j];
#pragma unroll
    for (int m = 0; m < 4; m++) {
        float2 hf = unpack2(hacc[m]);
        h[m] = make_float2(fmaxf(hf.x, 0.0f), fmaxf(hf.y, 0.0f));
        lg[m] = b2init;
    }
#pragma unroll
    for (int k = 0; k < 64; k++) {
        unsigned long long w2 = *(const unsigned long long*)&sW2[k * 64 + j];
#pragma unroll
        for (int m = 0; m < 4; m++) {
            float hv = __shfl_sync(0xffffffffu, (k & 1) ? h[m].y : h[m].x, k >> 1);
            fma2(lg[m], pack2(hv, hv), w2);
        }
    }
#pragma unroll
    for (int m = 0; m < 4; m++) {
        int n = n0 + m;
        float2 lgf = unpack2(lg[m]);
        float2 gmv = *(const float2*)&gum[n * 64 + j];
        float2 x2 = *(const float2*)&e2c[n * 64 + j];
        float gx = fsig(gmv.x + lgf.x);
        float gy = fsig(gmv.y + lgf.y);
        *(__half2*)&d_gatedh[n * 64 + j] = __floats2half2_rn(gx * x2.x, gy * x2.y);
    }
}

// ---------------------------------------------------------------------------
// K_edge_w: edge-parallel (CSR order), 8 threads/edge.
//   w[pos] = sigmoid(gum_csr[pos] + relu(Ph[h]+Qh[t])·W2)
// ---------------------------------------------------------------------------
__global__ __launch_bounds__(256) void k_edge_w(
    const float* __restrict__ W2,       // [64] layer slice
    const float* __restrict__ gum_csr)  // d_csr_gum[layer]
{
    __shared__ float sW2[64];
    if (threadIdx.x < 64) sW2[threadIdx.x] = W2[threadIdx.x];
    __syncthreads();

    int pos = blockIdx.x * 32 + (threadIdx.x >> 3);  // 25000 * 32 = 800000
    int sub = threadIdx.x & 7;
    int j = sub * 8;

    int h = d_csr_h[pos];
    int t = d_csr_t[pos];
    float p[8], q[8];
    ld_h8(&d_Ph[h * 64 + j], p);
    ld_h8(&d_Qh[t * 64 + j], q);

    float dot = 0.0f;
#pragma unroll
    for (int k = 0; k < 8; k++)
        dot = fmaf(fmaxf(p[k] + q[k], 0.0f), sW2[j + k], dot);
#pragma unroll
    for (int off = 4; off >= 1; off >>= 1)
        dot += __shfl_xor_sync(0xffffffffu, dot, off, 8);

    if (sub == 0)
        d_wcsr[pos] = fsig(gum_csr[pos] + dot);
}

// ---------------------------------------------------------------------------
// K_gather: per-node 3-branch SpMM + row norm + residual.
// 16 threads/node; NO shfl, NO expf — pure loads + FMAs.
// rowsum accumulated redundantly in every lane (broadcast reads).
// ---------------------------------------------------------------------------
__global__ __launch_bounds__(256) void k_gather(
    const float* __restrict__ e0c, const float* __restrict__ e1c,
    const float* __restrict__ e2c,
    const __half* __restrict__ e0h, const __half* __restrict__ e1h,
    float* __restrict__ e0n, float* __restrict__ e1n, float* __restrict__ e2n,
    __half* __restrict__ e0nh, __half* __restrict__ e1nh, int write_h)
{
    int node = blockIdx.x * 16 + (threadIdx.x >> 4);  // 6250 * 16 = 100000
    int sub = threadIdx.x & 15;
    int j = sub * 4;

    int start = d_rowptr[node];
    int deg = d_deg[node];

    float rowsum = 0.0f;
    float4 a0 = make_float4(0.f, 0.f, 0.f, 0.f);
    float4 a1 = a0, a2 = a0;

    for (int it = 0; it < deg; it++) {
        int pos = start + it;
        int t = d_csr_t[pos];
        float g = d_csr_g[pos];
        float w = d_wcsr[pos];
        rowsum += w;

        float4 f0 = ld_h4(&e0h[t * 64 + j]);
        a0.x = fmaf(g, f0.x, a0.x); a0.y = fmaf(g, f0.y, a0.y);
        a0.z = fmaf(g, f0.z, a0.z); a0.w = fmaf(g, f0.w, a0.w);
        float4 f1 = ld_h4(&e1h[t * 64 + j]);
        a1.x = fmaf(w, f1.x, a1.x); a1.y = fmaf(w, f1.y, a1.y);
        a1.z = fmaf(w, f1.z, a1.z); a1.w = fmaf(w, f1.w, a1.w);
        float4 f2 = ld_h4(&d_gatedh[t * 64 + j]);
        a2.x = fmaf(g, f2.x, a2.x); a2.y = fmaf(g, f2.y, a2.y);
        a2.z = fmaf(g, f2.z, a2.z); a2.w = fmaf(g, f2.w, a2.w);
    }

    float dinv = (rowsum > 0.0f) ? (1.0f / rowsum) : 0.0f;

    float4 c0 = *(const float4*)&e0c[node * 64 + j];
    float4 c1 = *(const float4*)&e1c[node * 64 + j];
    float4 c2 = *(const float4*)&e2c[node * 64 + j];

    float4 o0 = make_float4(c0.x + a0.x, c0.y + a0.y, c0.z + a0.z, c0.w + a0.w);
    float4 o1 = make_float4(fmaf(dinv, a1.x, c1.x), fmaf(dinv, a1.y, c1.y),
                            fmaf(dinv, a1.z, c1.z), fmaf(dinv, a1.w, c1.w));
    float4 o2 = make_float4(c2.x + a2.x, c2.y + a2.y, c2.z + a2.z, c2.w + a2.w);

    *(float4*)&e0n[node * 64 + j] = o0;
    *(float4*)&e1n[node * 64 + j] = o1;
    *(float4*)&e2n[node * 64 + j] = o2;
    if (write_h) {
        st_h4(&e0nh[node * 64 + j], o0);
        st_h4(&e1nh[node * 64 + j], o1);
    }
}

// ---------------------------------------------------------------------------
// K_finish: out[b] = emb0 + e_layer1[b] + e_layer2[b]
// ---------------------------------------------------------------------------
__global__ void k_finish(const float4* __restrict__ emb0, float4* __restrict__ out) {
    int i = blockIdx.x * blockDim.x + threadIdx.x;
    const int per = NN * (DD / 4);
    if (i >= per) return;
    float4 e = emb0[i];
#pragma unroll
    for (int b = 0; b < 3; b++) {
        float4 v1 = ((const float4*)d_eb[b][0])[i];
        float4 v2 = ((const float4*)d_eb[b][1])[i];
        out[b * per + i] = make_float4(e.x + v1.x + v2.x, e.y + v1.y + v2.y,
                                       e.z + v1.z + v2.z, e.w + v1.w + v2.w);
    }
}

// ---------------------------------------------------------------------------
// Host launcher (graph-capturable: launches only)
// ---------------------------------------------------------------------------
extern "C" void kernel_launch(void* const* d_in, const int* in_sizes, int n_in,
                              void* d_out, int out_size) {
    const float* emb0 = (const float*)d_in[0];
    const int*   hI   = (const int*)  d_in[1];
    const int*   tI   = (const int*)  d_in[2];
    const float* G    = (const float*)d_in[3];
    const float* egum = (const float*)d_in[4];   // [L,E]
    const float* ngum = (const float*)d_in[5];   // [L,N,D]
    const float* eW1  = (const float*)d_in[6];   // [L,128,64]
    const float* eb1  = (const float*)d_in[7];   // [L,64]
    const float* eW2  = (const float*)d_in[8];   // [L,64,1]
    const float* eb2  = (const float*)d_in[9];   // [L,1]
    const float* mW1  = (const float*)d_in[10];  // [L,64,64]
    const float* mb1  = (const float*)d_in[11];  // [L,64]
    const float* mW2  = (const float*)d_in[12];  // [L,64,64]
    const float* mb2  = (const float*)d_in[13];  // [L,64]
    float* out = (float*)d_out;

    // CSR build (once per launch)
    k_zero_deg<<<(NN + 255) / 256, 256>>>();
    k_count<<<(EE + 255) / 256, 256>>>(hI);
    k_scan<<<1, 1024>>>();
    k_fill<<<(EE + 255) / 256, 256>>>(hI, tI, G, egum, eb2);
    k_prep<<<(NN * DD / 4 + 255) / 256, 256>>>((const float4*)emb0);

    float* base;
    cudaGetSymbolAddress((void**)&base, d_eb);
    __half* h0base;
    cudaGetSymbolAddress((void**)&h0base, d_e0h);
    __half* h1base;
    cudaGetSymbolAddress((void**)&h1base, d_e1h);
    float* gumbase;
    cudaGetSymbolAddress((void**)&gumbase, d_csr_gum);

    float* ebuf[3][2];
    for (int b = 0; b < 3; b++)
        for (int s = 0; s < 2; s++)
            ebuf[b][s] = base + ((size_t)b * 2 + s) * (size_t)NN * DD;
    __half* e0hbuf[2] = { h0base, h0base + (size_t)NN * DD };
    __half* e1hbuf[2] = { h1base, h1base + (size_t)NN * DD };

    for (int i = 0; i < LLAYERS; i++) {
        const float* c0 = (i == 0) ? emb0 : ebuf[0][(i - 1) & 1];
        const float* c1 = (i == 0) ? emb0 : ebuf[1][(i - 1) & 1];
        const float* c2 = (i == 0) ? emb0 : ebuf[2][(i - 1) & 1];
        float* n0 = ebuf[0][i & 1];
        float* n1 = ebuf[1][i & 1];
        float* n2 = ebuf[2][i & 1];
        const __half* h0in = e0hbuf[i & 1];
        const __half* h1in = e1hbuf[i & 1];
        __half* h0out = e0hbuf[(i & 1) ^ 1];
        __half* h1out = e1hbuf[(i & 1) ^ 1];
        int write_h = (i + 1 < LLAYERS) ? 1 : 0;

        k_node_pq<<<3125, 256>>>(c1, eW1 + i * 128 * 64, eb1 + i * 64);
        k_node_gate<<<3125, 256>>>(c2, mW1 + i * 64 * 64, mb1 + i * 64,
                                   mW2 + i * 64 * 64, mb2 + i * 64,
                                   ngum + (size_t)i * NN * 64);
        k_edge_w<<<25000, 256>>>(eW2 + i * 64, gumbase + (size_t)i * EE);
        k_gather<<<6250, 256>>>(c0, c1, c2, h0in, h1in,
                                n0, n1, n2, h0out, h1out, write_h);
    }

    k_finish<<<(NN * DD / 4 + 255) / 256, 256>>>((const float4*)emb0, (float4*)out);
}

// round 5
// speedup vs baseline: 1.1622x; 1.0051x over previous
#include <cuda_runtime.h>
#include <cuda_fp16.h>

#define NN 100000      // nodes
#define DD 64          // feature dim
#define EE 800000      // edges
#define LLAYERS 2

// ---------------------------------------------------------------------------
// Scratch (device globals; no allocation anywhere)
// ---------------------------------------------------------------------------
__device__ float  d_eb[3][NN * DD];      // fp32 layer-1 output per branch
__device__ __half d_Ph[NN * DD];         // e1 @ W1_top + b1  (fp16)
__device__ __half d_Qh[NN * DD];         // e1 @ W1_bot       (fp16)
__device__ __half d_gatedh[NN * DD];     // gate * e2         (fp16)
__device__ __half d_e0h[2][NN * DD];     // fp16 gather mirrors
__device__ __half d_e1h[2][NN * DD];
__device__ int    d_deg[NN];
__device__ int    d_rowptr[NN];
__device__ int    d_cursor[NN];
__device__ int    d_csr_h[EE];
__device__ int    d_csr_t[EE];
__device__ float  d_csr_g[EE];
__device__ float  d_csr_gum[LLAYERS][EE];  // gumbel + b2, CSR order
__device__ float  d_wcsr[EE];              // edge weights, CSR order

__device__ __forceinline__ float fsig(float x) {
    return __fdividef(1.0f, 1.0f + __expf(-x));
}

// ---- packed f32x2 helpers (Blackwell) -------------------------------------
__device__ __forceinline__ unsigned long long pack2(float x, float y) {
    unsigned long long r;
    asm("mov.b64 %0,{%1,%2};" : "=l"(r) : "f"(x), "f"(y));
    return r;
}
__device__ __forceinline__ float2 unpack2(unsigned long long v) {
    float2 r;
    asm("mov.b64 {%0,%1},%2;" : "=f"(r.x), "=f"(r.y) : "l"(v));
    return r;
}
__device__ __forceinline__ void fma2(unsigned long long& d,
                                     unsigned long long a, unsigned long long b) {
    asm("fma.rn.f32x2 %0, %1, %2, %0;" : "+l"(d) : "l"(a), "l"(b));
}

// ---- fp16 quad/oct load, quad store ---------------------------------------
__device__ __forceinline__ float4 ld_h4(const __half* p) {
    uint2 r = *(const uint2*)p;
    __half2 h0 = *reinterpret_cast<__half2*>(&r.x);
    __half2 h1 = *reinterpret_cast<__half2*>(&r.y);
    float2 f0 = __half22float2(h0);
    float2 f1 = __half22float2(h1);
    return make_float4(f0.x, f0.y, f1.x, f1.y);
}
__device__ __forceinline__ void ld_h8(const __half* p, float* f) {
    uint4 r = *(const uint4*)p;
    float2 a = __half22float2(*reinterpret_cast<__half2*>(&r.x));
    float2 b = __half22float2(*reinterpret_cast<__half2*>(&r.y));
    float2 c = __half22float2(*reinterpret_cast<__half2*>(&r.z));
    float2 d = __half22float2(*reinterpret_cast<__half2*>(&r.w));
    f[0] = a.x; f[1] = a.y; f[2] = b.x; f[3] = b.y;
    f[4] = c.x; f[5] = c.y; f[6] = d.x; f[7] = d.y;
}
__device__ __forceinline__ void st_h4(__half* p, float4 v) {
    __half2 h0 = __floats2half2_rn(v.x, v.y);
    __half2 h1 = __floats2half2_rn(v.z, v.w);
    uint2 r;
    r.x = *reinterpret_cast<unsigned*>(&h0);
    r.y = *reinterpret_cast<unsigned*>(&h1);
    *(uint2*)p = r;
}

// ---------------------------------------------------------------------------
// CSR build + prep (fused zero/mirror kernel)
// ---------------------------------------------------------------------------
__global__ void k_zero_prep(const float4* __restrict__ emb0) {
    int i = blockIdx.x * blockDim.x + threadIdx.x;
    if (i < NN) d_deg[i] = 0;
    if (i < NN * DD / 4) {
        float4 v = emb0[i];
        st_h4(&d_e0h[0][i * 4], v);
        st_h4(&d_e1h[0][i * 4], v);
    }
}

__global__ void k_count(const int* __restrict__ h_idx) {
    int e = blockIdx.x * blockDim.x + threadIdx.x;
    if (e < EE) atomicAdd(&d_deg[h_idx[e]], 1);
}

__global__ void k_scan() {
    __shared__ int s[1024];
    int t = threadIdx.x;
    const int C = (NN + 1023) / 1024;
    int base = t * C;
    int sum = 0;
    for (int i = 0; i < C; i++) {
        int n = base + i;
        if (n < NN) sum += d_deg[n];
    }
    s[t] = sum;
    __syncthreads();
    for (int off = 1; off < 1024; off <<= 1) {
        int v = (t >= off) ? s[t - off] : 0;
        __syncthreads();
        s[t] += v;
        __syncthreads();
    }
    int run = s[t] - sum;  // exclusive prefix
    for (int i = 0; i < C; i++) {
        int n = base + i;
        if (n < NN) {
            d_rowptr[n] = run;
            d_cursor[n] = run;
            run += d_deg[n];
        }
    }
}

__global__ void k_fill(const int* __restrict__ h_idx, const int* __restrict__ t_idx,
                       const float* __restrict__ G,
                       const float* __restrict__ egum,  // [L,E]
                       const float* __restrict__ eb2)   // [L]
{
    int e = blockIdx.x * blockDim.x + threadIdx.x;
    if (e >= EE) return;
    int h = h_idx[e];
    int pos = atomicAdd(&d_cursor[h], 1);
    d_csr_h[pos] = h;
    d_csr_t[pos] = t_idx[e];
    d_csr_g[pos] = G[e];
    d_csr_gum[0][pos] = egum[e] + __ldg(&eb2[0]);
    d_csr_gum[1][pos] = egum[EE + e] + __ldg(&eb2[1]);
}

// ---------------------------------------------------------------------------
// K_node_pq: Ph = e1 @ W1_top + b1 ; Qh = e1 @ W1_bot  (fp16 outputs)
// Grid-stride: weights loaded ONCE per block, warp does 4 nodes per step.
// ---------------------------------------------------------------------------
__global__ __launch_bounds__(256) void k_node_pq(
    const float* __restrict__ e1c,
    const float* __restrict__ W1,   // [128,64] (top rows 0..63, bot 64..127)
    const float* __restrict__ b1)   // [64]
{
    __shared__ float sW[128 * 64];
    __shared__ float sB1[64];

    int tid = threadIdx.x;
    for (int i = tid; i < 128 * 64 / 4; i += blockDim.x)
        ((float4*)sW)[i] = ((const float4*)W1)[i];
    if (tid < 64) sB1[tid] = b1[tid];
    __syncthreads();

    int lane = tid & 31;
    int j = lane * 2;
    int gwarp = blockIdx.x * 8 + (tid >> 5);
    int nwarps = gridDim.x * 8;
    unsigned long long binit = *(const unsigned long long*)&sB1[j];

    for (int n0 = gwarp * 4; n0 < NN; n0 += nwarps * 4) {
        float a[4], b[4];
        unsigned long long p[4], q[4];
#pragma unroll
        for (int m = 0; m < 4; m++) {
            a[m] = e1c[(n0 + m) * 64 + lane];
            b[m] = e1c[(n0 + m) * 64 + 32 + lane];
            p[m] = binit;
            q[m] = pack2(0.0f, 0.0f);
        }
#pragma unroll
        for (int k = 0; k < 64; k++) {
            unsigned long long wt = *(const unsigned long long*)&sW[k * 64 + j];
            unsigned long long wb = *(const unsigned long long*)&sW[4096 + k * 64 + j];
#pragma unroll
            for (int m = 0; m < 4; m++) {
                float v = __shfl_sync(0xffffffffu, (k < 32) ? a[m] : b[m], k & 31);
                unsigned long long vv = pack2(v, v);
                fma2(p[m], vv, wt);
                fma2(q[m], vv, wb);
            }
        }
#pragma unroll
        for (int m = 0; m < 4; m++) {
            float2 pf = unpack2(p[m]);
            float2 qf = unpack2(q[m]);
            *(__half2*)&d_Ph[(n0 + m) * 64 + j] = __floats2half2_rn(pf.x, pf.y);
            *(__half2*)&d_Qh[(n0 + m) * 64 + j] = __floats2half2_rn(qf.x, qf.y);
        }
    }
}

// ---------------------------------------------------------------------------
// K_node_gate: gatedh = sigmoid(gum + relu(e2@W1+b1)@W2 + b2) * e2   (fp16)
// Grid-stride, weights loaded once per block.
// ---------------------------------------------------------------------------
__global__ __launch_bounds__(256) void k_node_gate(
    const float* __restrict__ e2c,
    const float* __restrict__ W1,   // [64,64]
    const float* __restrict__ b1,   // [64]
    const float* __restrict__ W2,   // [64,64]
    const float* __restrict__ b2,   // [64]
    const float* __restrict__ gum)  // [N,64] layer slice
{
    __shared__ float sW1[64 * 64];
    __shared__ float sW2[64 * 64];
    __shared__ float sB1[64], sB2[64];

    int tid = threadIdx.x;
    for (int i = tid; i < 64 * 64 / 4; i += blockDim.x) {
        ((float4*)sW1)[i] = ((const float4*)W1)[i];
        ((float4*)sW2)[i] = ((const float4*)W2)[i];
    }
    if (tid < 64) { sB1[tid] = b1[tid]; sB2[tid] = b2[tid]; }
    __syncthreads();

    int lane = tid & 31;
    int j = lane * 2;
    int gwarp = blockIdx.x * 8 + (tid >> 5);
    int nwarps = gridDim.x * 8;
    unsigned long long b1init = *(const unsigned long long*)&sB1[j];
    unsigned long long b2init = *(const unsigned long long*)&sB2[j];

    for (int n0 = gwarp * 4; n0 < NN; n0 += nwarps * 4) {
        float a[4], b[4];
        unsigned long long hacc[4];
#pragma unroll
        for (int m = 0; m < 4; m++) {
            a[m] = e2c[(n0 + m) * 64 + lane];
            b[m] = e2c[(n0 + m) * 64 + 32 + lane];
            hacc[m] = b1init;
        }
#pragma unroll
        for (int k = 0; k < 64; k++) {
            unsigned long long w1 = *(const unsigned long long*)&sW1[k * 64 + j];
#pragma unroll
            for (int m = 0; m < 4; m++) {
                float v = __shfl_sync(0xffffffffu, (k < 32) ? a[m] : b[m], k & 31);
                fma2(hacc[m], pack2(v, v), w1);
            }
        }
        float2 h[4];
        unsigned long long lg[4];
#pragma unroll
        for (int m = 0; m < 4; m++) {
            float2 hf = unpack2(hacc[m]);
            h[m] = make_float2(fmaxf(hf.x, 0.0f), fmaxf(hf.y, 0.0f));
            lg[m] = b2init;
        }
#pragma unroll
        for (int k = 0; k < 64; k++) {
            unsigned long long w2 = *(const unsigned long long*)&sW2[k * 64 + j];
#pragma unroll
            for (int m = 0; m < 4; m++) {
                float hv = __shfl_sync(0xffffffffu, (k & 1) ? h[m].y : h[m].x, k >> 1);
                fma2(lg[m], pack2(hv, hv), w2);
            }
        }
#pragma unroll
        for (int m = 0; m < 4; m++) {
            int n = n0 + m;
            float2 lgf = unpack2(lg[m]);
            float2 gmv = *(const float2*)&gum[n * 64 + j];
            float2 x2 = *(const float2*)&e2c[n * 64 + j];
            float gx = fsig(gmv.x + lgf.x);
            float gy = fsig(gmv.y + lgf.y);
            *(__half2*)&d_gatedh[n * 64 + j] = __floats2half2_rn(gx * x2.x, gy * x2.y);
        }
    }
}

// ---------------------------------------------------------------------------
// K_edge_w: edge-parallel (CSR order), 8 threads/edge.
// ---------------------------------------------------------------------------
__global__ __launch_bounds__(256) void k_edge_w(
    const float* __restrict__ W2,       // [64] layer slice
    const float* __restrict__ gum_csr)  // d_csr_gum[layer]
{
    __shared__ float sW2[64];
    if (threadIdx.x < 64) sW2[threadIdx.x] = W2[threadIdx.x];
    __syncthreads();

    int pos = blockIdx.x * 32 + (threadIdx.x >> 3);  // 25000 * 32 = 800000
    int sub = threadIdx.x & 7;
    int j = sub * 8;

    int h = d_csr_h[pos];
    int t = d_csr_t[pos];
    float p[8], q[8];
    ld_h8(&d_Ph[h * 64 + j], p);
    ld_h8(&d_Qh[t * 64 + j], q);

    float dot = 0.0f;
#pragma unroll
    for (int k = 0; k < 8; k++)
        dot = fmaf(fmaxf(p[k] + q[k], 0.0f), sW2[j + k], dot);
#pragma unroll
    for (int off = 4; off >= 1; off >>= 1)
        dot += __shfl_xor_sync(0xffffffffu, dot, off, 8);

    if (sub == 0)
        d_wcsr[pos] = fsig(gum_csr[pos] + dot);
}

// ---------------------------------------------------------------------------
// K_gather: per-node 3-branch SpMM + row norm + residual.
// Pipelined CSR loop (prefetch t/g/w one iter ahead). No shfl, no expf.
// last=0: write e*n fp32 + fp16 mirrors.   last=1: write out = emb0 + c + o.
// ---------------------------------------------------------------------------
__global__ __launch_bounds__(256) void k_gather(
    const float* __restrict__ e0c, const float* __restrict__ e1c,
    const float* __restrict__ e2c,
    const __half* __restrict__ e0h, const __half* __restrict__ e1h,
    float* __restrict__ e0n, float* __restrict__ e1n, float* __restrict__ e2n,
    __half* __restrict__ e0nh, __half* __restrict__ e1nh,
    const float* __restrict__ emb0, float* __restrict__ out, int last)
{
    int node = blockIdx.x * 16 + (threadIdx.x >> 4);  // 6250 * 16 = 100000
    int sub = threadIdx.x & 15;
    int j = sub * 4;

    int start = d_rowptr[node];
    int deg = d_deg[node];

    float rowsum = 0.0f;
    float4 a0 = make_float4(0.f, 0.f, 0.f, 0.f);
    float4 a1 = a0, a2 = a0;

    int t = 0; float g = 0.f, w = 0.f;
    if (deg > 0) {
        t = d_csr_t[start]; g = d_csr_g[start]; w = d_wcsr[start];
    }
    for (int it = 0; it < deg; it++) {
        int tc = t; float gc = g, wc = w;
        int pos = start + it + 1;
        if (it + 1 < deg) {
            t = d_csr_t[pos]; g = d_csr_g[pos]; w = d_wcsr[pos];
        }
        rowsum += wc;

        float4 f0 = ld_h4(&e0h[tc * 64 + j]);
        a0.x = fmaf(gc, f0.x, a0.x); a0.y = fmaf(gc, f0.y, a0.y);
        a0.z = fmaf(gc, f0.z, a0.z); a0.w = fmaf(gc, f0.w, a0.w);
        float4 f1 = ld_h4(&e1h[tc * 64 + j]);
        a1.x = fmaf(wc, f1.x, a1.x); a1.y = fmaf(wc, f1.y, a1.y);
        a1.z = fmaf(wc, f1.z, a1.z); a1.w = fmaf(wc, f1.w, a1.w);
        float4 f2 = ld_h4(&d_gatedh[tc * 64 + j]);
        a2.x = fmaf(gc, f2.x, a2.x); a2.y = fmaf(gc, f2.y, a2.y);
        a2.z = fmaf(gc, f2.z, a2.z); a2.w = fmaf(gc, f2.w, a2.w);
    }

    float dinv = (rowsum > 0.0f) ? (1.0f / rowsum) : 0.0f;

    float4 c0 = *(const float4*)&e0c[node * 64 + j];
    float4 c1 = *(const float4*)&e1c[node * 64 + j];
    float4 c2 = *(const float4*)&e2c[node * 64 + j];

    float4 o0 = make_float4(c0.x + a0.x, c0.y + a0.y, c0.z + a0.z, c0.w + a0.w);
    float4 o1 = make_float4(fmaf(dinv, a1.x, c1.x), fmaf(dinv, a1.y, c1.y),
                            fmaf(dinv, a1.z, c1.z), fmaf(dinv, a1.w, c1.w));
    float4 o2 = make_float4(c2.x + a2.x, c2.y + a2.y, c2.z + a2.z, c2.w + a2.w);

    if (!last) {
        *(float4*)&e0n[node * 64 + j] = o0;
        *(float4*)&e1n[node * 64 + j] = o1;
        *(float4*)&e2n[node * 64 + j] = o2;
        st_h4(&e0nh[node * 64 + j], o0);
        st_h4(&e1nh[node * 64 + j], o1);
    } else {
        // out[b] = emb0 + e_after_l1 (=c) + e_after_l2 (=o)
        float4 z = *(const float4*)&emb0[node * 64 + j];
        const int per = NN * DD;
        *(float4*)&out[0 * per + node * 64 + j] =
            make_float4(z.x + c0.x + o0.x, z.y + c0.y + o0.y,
                        z.z + c0.z + o0.z, z.w + c0.w + o0.w);
        *(float4*)&out[1 * per + node * 64 + j] =
            make_float4(z.x + c1.x + o1.x, z.y + c1.y + o1.y,
                        z.z + c1.z + o1.z, z.w + c1.w + o1.w);
        *(float4*)&out[2 * per + node * 64 + j] =
            make_float4(z.x + c2.x + o2.x, z.y + c2.y + o2.y,
                        z.z + c2.z + o2.z, z.w + c2.w + o2.w);
    }
}

// ---------------------------------------------------------------------------
// Host launcher (graph-capturable: launches only)
// ---------------------------------------------------------------------------
extern "C" void kernel_launch(void* const* d_in, const int* in_sizes, int n_in,
                              void* d_out, int out_size) {
    const float* emb0 = (const float*)d_in[0];
    const int*   hI   = (const int*)  d_in[1];
    const int*   tI   = (const int*)  d_in[2];
    const float* G    = (const float*)d_in[3];
    const float* egum = (const float*)d_in[4];   // [L,E]
    const float* ngum = (const float*)d_in[5];   // [L,N,D]
    const float* eW1  = (const float*)d_in[6];   // [L,128,64]
    const float* eb1  = (const float*)d_in[7];   // [L,64]
    const float* eW2  = (const float*)d_in[8];   // [L,64,1]
    const float* eb2  = (const float*)d_in[9];   // [L,1]
    const float* mW1  = (const float*)d_in[10];  // [L,64,64]
    const float* mb1  = (const float*)d_in[11];  // [L,64]
    const float* mW2  = (const float*)d_in[12];  // [L,64,64]
    const float* mb2  = (const float*)d_in[13];  // [L,64]
    float* out = (float*)d_out;

    // CSR build + fp16 mirror prep
    k_zero_prep<<<(NN * DD / 4 + 255) / 256, 256>>>((const float4*)emb0);
    k_count<<<(EE + 255) / 256, 256>>>(hI);
    k_scan<<<1, 1024>>>();
    k_fill<<<(EE + 255) / 256, 256>>>(hI, tI, G, egum, eb2);

    float* base;
    cudaGetSymbolAddress((void**)&base, d_eb);
    __half* h0base;
    cudaGetSymbolAddress((void**)&h0base, d_e0h);
    __half* h1base;
    cudaGetSymbolAddress((void**)&h1base, d_e1h);
    float* gumbase;
    cudaGetSymbolAddress((void**)&gumbase, d_csr_gum);

    float* ebuf[3];
    for (int b = 0; b < 3; b++)
        ebuf[b] = base + (size_t)b * NN * DD;
    __half* e0hbuf[2] = { h0base, h0base + (size_t)NN * DD };
    __half* e1hbuf[2] = { h1base, h1base + (size_t)NN * DD };

    for (int i = 0; i < LLAYERS; i++) {
        int last = (i == LLAYERS - 1);
        const float* c0 = (i == 0) ? emb0 : ebuf[0];
        const float* c1 = (i == 0) ? emb0 : ebuf[1];
        const float* c2 = (i == 0) ? emb0 : ebuf[2];

        k_node_pq<<<592, 256>>>(c1, eW1 + i * 128 * 64, eb1 + i * 64);
        k_node_gate<<<592, 256>>>(c2, mW1 + i * 64 * 64, mb1 + i * 64,
                                  mW2 + i * 64 * 64, mb2 + i * 64,
                                  ngum + (size_t)i * NN * 64);
        k_edge_w<<<25000, 256>>>(eW2 + i * 64, gumbase + (size_t)i * EE);
        k_gather<<<6250, 256>>>(c0, c1, c2, e0hbuf[i], e1hbuf[i],
                                ebuf[0], ebuf[1], ebuf[2],
                                e0hbuf[i ^ 1], e1hbuf[i ^ 1],
                                emb0, out, last);
    }
}

// round 6
// speedup vs baseline: 1.5456x; 1.3299x over previous
#include <cuda_runtime.h>
#include <cuda_fp16.h>

#define NN 100000      // nodes
#define DD 64          // feature dim
#define EE 800000      // edges

#define SCAN_BLOCKS 98          // ceil(NN / 1024)
#define CHUNK 1024
#define FILL_BLOCKS 298         // blocks [0,298) do scan(+)fill in L2
#define EDGEW_BLOCKS 412        // blocks [298,710) do edge weights in L2
#define L2_GRID (FILL_BLOCKS + EDGEW_BLOCKS)

// ---------------------------------------------------------------------------
// Scratch (device globals; no allocation anywhere)
// ---------------------------------------------------------------------------
__device__ float  d_eb[3][NN * DD];      // fp32 layer-1 output per branch
__device__ __half d_Ph[NN * DD];         // e1 @ W1_top + b1  (fp16)
__device__ __half d_Qh[NN * DD];         // e1 @ W1_bot       (fp16)
__device__ __half d_gatedh[NN * DD];     // gate * e2         (fp16)
__device__ __half d_e0h[2][NN * DD];     // fp16 gather mirrors
__device__ __half d_e1h[2][NN * DD];
__device__ int    d_deg[NN];
__device__ int    d_rowptr[NN];
__device__ int    d_cursor[NN];
__device__ int    d_csr_t[EE];
__device__ int    d_csr_eid[EE];
__device__ float  d_csr_g[EE];
__device__ float  d_w[EE];               // edge weights, ORIGINAL edge order
__device__ int    d_agg[SCAN_BLOCKS];    // decoupled-lookback state
__device__ int    d_aggflag[SCAN_BLOCKS];
__device__ int    d_chunkdone[SCAN_BLOCKS];

__device__ __forceinline__ float fsig(float x) {
    return __fdividef(1.0f, 1.0f + __expf(-x));
}

// ---- packed f32x2 helpers --------------------------------------------------
__device__ __forceinline__ unsigned long long pack2(float x, float y) {
    unsigned long long r;
    asm("mov.b64 %0,{%1,%2};" : "=l"(r) : "f"(x), "f"(y));
    return r;
}
__device__ __forceinline__ float2 unpack2(unsigned long long v) {
    float2 r;
    asm("mov.b64 {%0,%1},%2;" : "=f"(r.x), "=f"(r.y) : "l"(v));
    return r;
}
__device__ __forceinline__ void fma2(unsigned long long& d,
                                     unsigned long long a, unsigned long long b) {
    asm("fma.rn.f32x2 %0, %1, %2, %0;" : "+l"(d) : "l"(a), "l"(b));
}

// ---- fp16 vector load/store ------------------------------------------------
__device__ __forceinline__ void ld_h8(const __half* p, float* f) {
    uint4 r = *(const uint4*)p;
    float2 a = __half22float2(*reinterpret_cast<__half2*>(&r.x));
    float2 b = __half22float2(*reinterpret_cast<__half2*>(&r.y));
    float2 c = __half22float2(*reinterpret_cast<__half2*>(&r.z));
    float2 d = __half22float2(*reinterpret_cast<__half2*>(&r.w));
    f[0] = a.x; f[1] = a.y; f[2] = b.x; f[3] = b.y;
    f[4] = c.x; f[5] = c.y; f[6] = d.x; f[7] = d.y;
}
__device__ __forceinline__ void st_h4(__half* p, float4 v) {
    __half2 h0 = __floats2half2_rn(v.x, v.y);
    __half2 h1 = __floats2half2_rn(v.z, v.w);
    uint2 r;
    r.x = *reinterpret_cast<unsigned*>(&h0);
    r.y = *reinterpret_cast<unsigned*>(&h1);
    *(uint2*)p = r;
}
__device__ __forceinline__ void st_h8(__half* p, const float* f) {
    __half2 h0 = __floats2half2_rn(f[0], f[1]);
    __half2 h1 = __floats2half2_rn(f[2], f[3]);
    __half2 h2 = __floats2half2_rn(f[4], f[5]);
    __half2 h3 = __floats2half2_rn(f[6], f[7]);
    uint4 r;
    r.x = *reinterpret_cast<unsigned*>(&h0);
    r.y = *reinterpret_cast<unsigned*>(&h1);
    r.z = *reinterpret_cast<unsigned*>(&h2);
    r.w = *reinterpret_cast<unsigned*>(&h3);
    *(uint4*)p = r;
}

// ---------------------------------------------------------------------------
// L0: zero deg + lookback flags, build fp16 mirrors of emb0
// ---------------------------------------------------------------------------
__global__ void k_pre(const float4* __restrict__ emb0) {
    int i = blockIdx.x * blockDim.x + threadIdx.x;
    if (i < NN) d_deg[i] = 0;
    if (i < SCAN_BLOCKS) { d_aggflag[i] = 0; d_chunkdone[i] = 0; }
    if (i < NN * DD / 4) {
        float4 v = emb0[i];
        st_h4(&d_e0h[0][i * 4], v);
        st_h4(&d_e1h[0][i * 4], v);
    }
}

// ---------------------------------------------------------------------------
// L1 / L4: fused MLPs (+ optional degree count).
// blocks [0,296): pq      blocks [296,592): gate     blocks [592,792): count
// ---------------------------------------------------------------------------
__global__ __launch_bounds__(256) void k_mlp(
    const float* __restrict__ e1c, const float* __restrict__ e2c,
    const float* __restrict__ eW1, const float* __restrict__ eb1,  // [128,64],[64]
    const float* __restrict__ mW1, const float* __restrict__ mb1,  // [64,64],[64]
    const float* __restrict__ mW2, const float* __restrict__ mb2,  // [64,64],[64]
    const float* __restrict__ ngum,                                // [N,64]
    const int* __restrict__ h_idx)                                 // may be unused
{
    __shared__ float sW[128 * 64];   // pq: full W1. gate: [0..4095]=W1, [4096..]=W2
    __shared__ float sBa[64], sBb[64];

    int tid = threadIdx.x;
    int bid = blockIdx.x;

    if (bid >= 592) {  // count
        for (int e = (bid - 592) * 256 + tid; e < EE; e += 200 * 256)
            atomicAdd(&d_deg[h_idx[e]], 1);
        return;
    }

    int lane = tid & 31;
    int j = lane * 2;

    if (bid < 296) {
        // ---- pq: Ph = e1 @ W1_top + b1 ; Qh = e1 @ W1_bot ----
        for (int i = tid; i < 128 * 64 / 4; i += 256)
            ((float4*)sW)[i] = ((const float4*)eW1)[i];
        if (tid < 64) sBa[tid] = eb1[tid];
        __syncthreads();

        int gwarp = bid * 8 + (tid >> 5);
        int nwarps = 296 * 8;
        unsigned long long binit = *(const unsigned long long*)&sBa[j];

        for (int n0 = gwarp * 4; n0 < NN; n0 += nwarps * 4) {
            float a[4], b[4];
            unsigned long long p[4], q[4];
#pragma unroll
            for (int m = 0; m < 4; m++) {
                a[m] = e1c[(n0 + m) * 64 + lane];
                b[m] = e1c[(n0 + m) * 64 + 32 + lane];
                p[m] = binit;
                q[m] = pack2(0.0f, 0.0f);
            }
#pragma unroll
            for (int k = 0; k < 64; k++) {
                unsigned long long wt = *(const unsigned long long*)&sW[k * 64 + j];
                unsigned long long wb = *(const unsigned long long*)&sW[4096 + k * 64 + j];
#pragma unroll
                for (int m = 0; m < 4; m++) {
                    float v = __shfl_sync(0xffffffffu, (k < 32) ? a[m] : b[m], k & 31);
                    unsigned long long vv = pack2(v, v);
                    fma2(p[m], vv, wt);
                    fma2(q[m], vv, wb);
                }
            }
#pragma unroll
            for (int m = 0; m < 4; m++) {
                float2 pf = unpack2(p[m]);
                float2 qf = unpack2(q[m]);
                *(__half2*)&d_Ph[(n0 + m) * 64 + j] = __floats2half2_rn(pf.x, pf.y);
                *(__half2*)&d_Qh[(n0 + m) * 64 + j] = __floats2half2_rn(qf.x, qf.y);
            }
        }
    } else {
        // ---- gate: gatedh = sigmoid(gum + relu(e2@W1+b1)@W2 + b2) * e2 ----
        for (int i = tid; i < 64 * 64 / 4; i += 256) {
            ((float4*)sW)[i] = ((const float4*)mW1)[i];
            ((float4*)(sW + 4096))[i] = ((const float4*)mW2)[i];
        }
        if (tid < 64) { sBa[tid] = mb1[tid]; sBb[tid] = mb2[tid]; }
        __syncthreads();

        int gwarp = (bid - 296) * 8 + (tid >> 5);
        int nwarps = 296 * 8;
        unsigned long long b1init = *(const unsigned long long*)&sBa[j];
        unsigned long long b2init = *(const unsigned long long*)&sBb[j];

        for (int n0 = gwarp * 4; n0 < NN; n0 += nwarps * 4) {
            float a[4], b[4];
            unsigned long long hacc[4];
#pragma unroll
            for (int m = 0; m < 4; m++) {
                a[m] = e2c[(n0 + m) * 64 + lane];
                b[m] = e2c[(n0 + m) * 64 + 32 + lane];
                hacc[m] = b1init;
            }
#pragma unroll
            for (int k = 0; k < 64; k++) {
                unsigned long long w1 = *(const unsigned long long*)&sW[k * 64 + j];
#pragma unroll
                for (int m = 0; m < 4; m++) {
                    float v = __shfl_sync(0xffffffffu, (k < 32) ? a[m] : b[m], k & 31);
                    fma2(hacc[m], pack2(v, v), w1);
                }
            }
            float2 h[4];
            unsigned long long lg[4];
#pragma unroll
            for (int m = 0; m < 4; m++) {
                float2 hf = unpack2(hacc[m]);
                h[m] = make_float2(fmaxf(hf.x, 0.0f), fmaxf(hf.y, 0.0f));
                lg[m] = b2init;
            }
#pragma unroll
            for (int k = 0; k < 64; k++) {
                unsigned long long w2 = *(const unsigned long long*)&sW[4096 + k * 64 + j];
#pragma unroll
                for (int m = 0; m < 4; m++) {
                    float hv = __shfl_sync(0xffffffffu, (k & 1) ? h[m].y : h[m].x, k >> 1);
                    fma2(lg[m], pack2(hv, hv), w2);
                }
            }
#pragma unroll
            for (int m = 0; m < 4; m++) {
                int n = n0 + m;
                float2 lgf = unpack2(lg[m]);
                float2 gmv = *(const float2*)&ngum[n * 64 + j];
                float2 x2 = *(const float2*)&e2c[n * 64 + j];
                float gx = fsig(gmv.x + lgf.x);
                float gy = fsig(gmv.y + lgf.y);
                *(__half2*)&d_gatedh[n * 64 + j] = __floats2half2_rn(gx * x2.x, gy * x2.y);
            }
        }
    }
}

// ---------------------------------------------------------------------------
// Edge weights in ORIGINAL order: w[e] = sigmoid(gum[e] + b2 + relu(P[h]+Q[t])·W2)
// 8 threads/edge; callable as a device helper from two kernels.
// ---------------------------------------------------------------------------
__device__ __forceinline__ void edgew_body(
    int block0, int nblocks,
    const int* __restrict__ h_idx, const int* __restrict__ t_idx,
    const float* __restrict__ gum, float b2, const float* sW2)
{
    int tid = threadIdx.x;
    int sub = tid & 7;
    int grp = tid >> 3;
    int j = sub * 8;

    for (int e = (blockIdx.x - block0) * 32 + grp; e < EE; e += nblocks * 32) {
        int h = h_idx[e];
        int t = t_idx[e];
        float p[8], q[8];
        ld_h8(&d_Ph[h * 64 + j], p);
        ld_h8(&d_Qh[t * 64 + j], q);
        float dot = 0.0f;
#pragma unroll
        for (int k = 0; k < 8; k++)
            dot = fmaf(fmaxf(p[k] + q[k], 0.0f), sW2[j + k], dot);
#pragma unroll
        for (int off = 4; off >= 1; off >>= 1)
            dot += __shfl_xor_sync(0xffffffffu, dot, off, 8);
        if (sub == 0)
            d_w[e] = fsig(gum[e] + b2 + dot);
    }
}

// ---------------------------------------------------------------------------
// L2: decoupled-lookback CSR scan + fill, overlapped with layer-0 edge weights.
// blocks [0,98): scan own 1024-node chunk, then join fill
// blocks [98,298): fill (spin on chunk-ready flags)
// blocks [298,710): edge weights (original order)
// ---------------------------------------------------------------------------
__global__ __launch_bounds__(256) void k_build_edgew(
    const int* __restrict__ h_idx, const int* __restrict__ t_idx,
    const float* __restrict__ G,
    const float* __restrict__ gum,  // egum layer slice
    const float* __restrict__ W2, const float* __restrict__ b2p)
{
    __shared__ int sScan[256];
    __shared__ int sRed[256];
    __shared__ float sW2[64];

    int tid = threadIdx.x;
    int bid = blockIdx.x;

    if (bid >= FILL_BLOCKS) {
        // ---------------- edge weights ----------------
        if (tid < 64) sW2[tid] = W2[tid];
        __syncthreads();
        float b2 = __ldg(b2p);
        edgew_body(FILL_BLOCKS, EDGEW_BLOCKS, h_idx, t_idx, gum, b2, sW2);
        return;
    }

    if (bid < SCAN_BLOCKS) {
        // ---------------- lookback scan for chunk bid ----------------
        int nbase = bid * CHUNK + tid * 4;
        int d0 = 0, d1 = 0, d2 = 0, d3 = 0;
        if (nbase + 0 < NN) d0 = d_deg[nbase + 0];
        if (nbase + 1 < NN) d1 = d_deg[nbase + 1];
        if (nbase + 2 < NN) d2 = d_deg[nbase + 2];
        if (nbase + 3 < NN) d3 = d_deg[nbase + 3];
        int mysum = d0 + d1 + d2 + d3;
        sScan[tid] = mysum;
        __syncthreads();
        for (int off = 1; off < 256; off <<= 1) {
            int v = (tid >= off) ? sScan[tid - off] : 0;
            __syncthreads();
            sScan[tid] += v;
            __syncthreads();
        }
        int excl = sScan[tid] - mysum;
        if (tid == 255) {
            d_agg[bid] = sScan[255];
            __threadfence();
            *((volatile int*)&d_aggflag[bid]) = 1;
        }
        // sum predecessor aggregates
        int pv = 0;
        if (tid < bid) {
            while (*((volatile int*)&d_aggflag[tid]) == 0) { }
            pv = d_agg[tid];
        }
        sRed[tid] = pv;
        __syncthreads();
        for (int off = 128; off >= 1; off >>= 1) {
            if (tid < off) sRed[tid] += sRed[tid + off];
            __syncthreads();
        }
        int run = sRed[0] + excl;
        if (nbase + 0 < NN) { d_rowptr[nbase + 0] = run; d_cursor[nbase + 0] = run; run += d0; }
        if (nbase + 1 < NN) { d_rowptr[nbase + 1] = run; d_cursor[nbase + 1] = run; run += d1; }
        if (nbase + 2 < NN) { d_rowptr[nbase + 2] = run; d_cursor[nbase + 2] = run; run += d2; }
        if (nbase + 3 < NN) { d_rowptr[nbase + 3] = run; d_cursor[nbase + 3] = run; run += d3; }
        __threadfence();
        __syncthreads();
        if (tid == 0) *((volatile int*)&d_chunkdone[bid]) = 1;
    }

    // ---------------- fill (all blocks [0,298), spin per chunk) ----------------
    for (int e = bid * 256 + tid; e < EE; e += FILL_BLOCKS * 256) {
        int h = h_idx[e];
        int c = h >> 10;
        while (*((volatile int*)&d_chunkdone[c]) == 0) { }
        int pos = atomicAdd(&d_cursor[h], 1);
        d_csr_t[pos] = t_idx[e];
        d_csr_g[pos] = G[e];
        d_csr_eid[pos] = e;
    }
}

// ---------------------------------------------------------------------------
// L5: standalone edge weights for layer 1
// ---------------------------------------------------------------------------
__global__ __launch_bounds__(256) void k_edgew(
    const int* __restrict__ h_idx, const int* __restrict__ t_idx,
    const float* __restrict__ gum,
    const float* __restrict__ W2, const float* __restrict__ b2p)
{
    __shared__ float sW2[64];
    if (threadIdx.x < 64) sW2[threadIdx.x] = W2[threadIdx.x];
    __syncthreads();
    float b2 = __ldg(b2p);
    edgew_body(0, 1184, h_idx, t_idx, gum, b2, sW2);
}

// ---------------------------------------------------------------------------
// L3/L6: per-node 3-branch SpMM + row norm + residual.  8 threads/node.
// last=0: write fp32 state + fp16 mirrors.   last=1: out = emb0 + c + o.
// ---------------------------------------------------------------------------
__global__ __launch_bounds__(256) void k_gather(
    const float* __restrict__ e0c, const float* __restrict__ e1c,
    const float* __restrict__ e2c,
    const __half* __restrict__ e0h, const __half* __restrict__ e1h,
    float* __restrict__ e0n, float* __restrict__ e1n, float* __restrict__ e2n,
    __half* __restrict__ e0nh, __half* __restrict__ e1nh,
    const float* __restrict__ emb0, float* __restrict__ out, int last)
{
    int node = blockIdx.x * 32 + (threadIdx.x >> 3);  // 3125 * 32 = 100000
    int sub = threadIdx.x & 7;
    int j = sub * 8;

    int start = d_rowptr[node];
    int deg = d_deg[node];

    float rowsum = 0.0f;
    float a0[8], a1[8], a2[8];
#pragma unroll
    for (int k = 0; k < 8; k++) { a0[k] = 0.f; a1[k] = 0.f; a2[k] = 0.f; }

    int t = 0; float g = 0.f, w = 0.f;
    if (deg > 0) {
        t = d_csr_t[start]; g = d_csr_g[start];
        w = d_w[d_csr_eid[start]];
    }
    for (int it = 0; it < deg; it++) {
        int tc = t; float gc = g, wc = w;
        if (it + 1 < deg) {
            int pos = start + it + 1;
            t = d_csr_t[pos]; g = d_csr_g[pos];
            w = d_w[d_csr_eid[pos]];
        }
        rowsum += wc;
        float f[8];
        ld_h8(&e0h[tc * 64 + j], f);
#pragma unroll
        for (int k = 0; k < 8; k++) a0[k] = fmaf(gc, f[k], a0[k]);
        ld_h8(&e1h[tc * 64 + j], f);
#pragma unroll
        for (int k = 0; k < 8; k++) a1[k] = fmaf(wc, f[k], a1[k]);
        ld_h8(&d_gatedh[tc * 64 + j], f);
#pragma unroll
        for (int k = 0; k < 8; k++) a2[k] = fmaf(gc, f[k], a2[k]);
    }

    float dinv = (rowsum > 0.0f) ? (1.0f / rowsum) : 0.0f;

    float c0[8], c1[8], c2[8], o0[8], o1[8], o2[8];
    *(float4*)&c0[0] = *(const float4*)&e0c[node * 64 + j];
    *(float4*)&c0[4] = *(const float4*)&e0c[node * 64 + j + 4];
    *(float4*)&c1[0] = *(const float4*)&e1c[node * 64 + j];
    *(float4*)&c1[4] = *(const float4*)&e1c[node * 64 + j + 4];
    *(float4*)&c2[0] = *(const float4*)&e2c[node * 64 + j];
    *(float4*)&c2[4] = *(const float4*)&e2c[node * 64 + j + 4];
#pragma unroll
    for (int k = 0; k < 8; k++) {
        o0[k] = c0[k] + a0[k];
        o1[k] = fmaf(dinv, a1[k], c1[k]);
        o2[k] = c2[k] + a2[k];
    }

    if (!last) {
        *(float4*)&e0n[node * 64 + j]     = *(float4*)&o0[0];
        *(float4*)&e0n[node * 64 + j + 4] = *(float4*)&o0[4];
        *(float4*)&e1n[node * 64 + j]     = *(float4*)&o1[0];
        *(float4*)&e1n[node * 64 + j + 4] = *(float4*)&o1[4];
        *(float4*)&e2n[node * 64 + j]     = *(float4*)&o2[0];
        *(float4*)&e2n[node * 64 + j + 4] = *(float4*)&o2[4];
        st_h8(&e0nh[node * 64 + j], o0);
        st_h8(&e1nh[node * 64 + j], o1);
    } else {
        float z[8];
        *(float4*)&z[0] = *(const float4*)&emb0[node * 64 + j];
        *(float4*)&z[4] = *(const float4*)&emb0[node * 64 + j + 4];
        const int per = NN * DD;
        float r[8];
#pragma unroll
        for (int k = 0; k < 8; k++) r[k] = z[k] + c0[k] + o0[k];
        *(float4*)&out[0 * per + node * 64 + j]     = *(float4*)&r[0];
        *(float4*)&out[0 * per + node * 64 + j + 4] = *(float4*)&r[4];
#pragma unroll
        for (int k = 0; k < 8; k++) r[k] = z[k] + c1[k] + o1[k];
        *(float4*)&out[1 * per + node * 64 + j]     = *(float4*)&r[0];
        *(float4*)&out[1 * per + node * 64 + j + 4] = *(float4*)&r[4];
#pragma unroll
        for (int k = 0; k < 8; k++) r[k] = z[k] + c2[k] + o2[k];
        *(float4*)&out[2 * per + node * 64 + j]     = *(float4*)&r[0];
        *(float4*)&out[2 * per + node * 64 + j + 4] = *(float4*)&r[4];
    }
}

// ---------------------------------------------------------------------------
// Host launcher (graph-capturable: launches only)
// ---------------------------------------------------------------------------
extern "C" void kernel_launch(void* const* d_in, const int* in_sizes, int n_in,
                              void* d_out, int out_size) {
    const float* emb0 = (const float*)d_in[0];
    const int*   hI   = (const int*)  d_in[1];
    const int*   tI   = (const int*)  d_in[2];
    const float* G    = (const float*)d_in[3];
    const float* egum = (const float*)d_in[4];   // [L,E]
    const float* ngum = (const float*)d_in[5];   // [L,N,D]
    const float* eW1  = (const float*)d_in[6];   // [L,128,64]
    const float* eb1  = (const float*)d_in[7];   // [L,64]
    const float* eW2  = (const float*)d_in[8];   // [L,64,1]
    const float* eb2  = (const float*)d_in[9];   // [L,1]
    const float* mW1  = (const float*)d_in[10];  // [L,64,64]
    const float* mb1  = (const float*)d_in[11];  // [L,64]
    const float* mW2  = (const float*)d_in[12];  // [L,64,64]
    const float* mb2  = (const float*)d_in[13];  // [L,64]
    float* out = (float*)d_out;

    float* base;
    cudaGetSymbolAddress((void**)&base, d_eb);
    __half* h0base;
    cudaGetSymbolAddress((void**)&h0base, d_e0h);
    __half* h1base;
    cudaGetSymbolAddress((void**)&h1base, d_e1h);
    float* ebuf[3];
    for (int b = 0; b < 3; b++)
        ebuf[b] = base + (size_t)b * NN * DD;
    __half* e0hbuf[2] = { h0base, h0base + (size_t)NN * DD };
    __half* e1hbuf[2] = { h1base, h1base + (size_t)NN * DD };

    // L0: zero + mirrors + flags
    k_pre<<<(NN * DD / 4 + 255) / 256, 256>>>((const float4*)emb0);

    // L1: layer-0 MLPs + degree count
    k_mlp<<<792, 256>>>(emb0, emb0, eW1, eb1, mW1, mb1, mW2, mb2, ngum, hI);

    // L2: CSR scan+fill overlapped with layer-0 edge weights
    k_build_edgew<<<L2_GRID, 256>>>(hI, tI, G, egum, eW2, eb2);

    // L3: layer-0 gather  <-- profiled launch (index 3)
    k_gather<<<3125, 256>>>(emb0, emb0, emb0, e0hbuf[0], e1hbuf[0],
                            ebuf[0], ebuf[1], ebuf[2],
                            e0hbuf[1], e1hbuf[1],
                            emb0, out, 0);

    // L4: layer-1 MLPs (no count blocks)
    k_mlp<<<592, 256>>>(ebuf[1], ebuf[2],
                        eW1 + 128 * 64, eb1 + 64,
                        mW1 + 64 * 64, mb1 + 64, mW2 + 64 * 64, mb2 + 64,
                        ngum + (size_t)NN * 64, hI);

    // L5: layer-1 edge weights
    k_edgew<<<1184, 256>>>(hI, tI, egum + EE, eW2 + 64, eb2 + 1);

    // L6: layer-1 gather + final output
    k_gather<<<3125, 256>>>(ebuf[0], ebuf[1], ebuf[2], e0hbuf[1], e1hbuf[1],
                            ebuf[0], ebuf[1], ebuf[2],
                            e0hbuf[0], e1hbuf[0],
                            emb0, out, 1);
}

// round 7
// speedup vs baseline: 1.5637x; 1.0117x over previous
#include <cuda_runtime.h>
#include <cuda_fp16.h>

#define NN 100000      // nodes
#define DD 64          // feature dim
#define EE 800000      // edges

#define SCAN_BLOCKS 98          // ceil(NN / 1024)
#define CHUNK 1024
#define FILL_BLOCKS 298         // blocks [0,298) do scan(+)fill in L2
#define EDGEW_BLOCKS 412        // blocks [298,710) do edge weights in L2
#define L2_GRID (FILL_BLOCKS + EDGEW_BLOCKS)

// ---------------------------------------------------------------------------
// Scratch (device globals; no allocation anywhere)
// ---------------------------------------------------------------------------
__device__ float  d_eb[3][NN * DD];      // fp32 layer-1 output per branch
__device__ __half d_Ph[NN * DD];         // e1 @ W1_top + b1  (fp16)
__device__ __half d_Qh[NN * DD];         // e1 @ W1_bot       (fp16)
__device__ __half d_gatedh[NN * DD];     // gate * e2         (fp16)
__device__ __half d_e0h[2][NN * DD];     // fp16 gather mirrors
__device__ __half d_e1h[2][NN * DD];
__device__ int    d_deg[NN];
__device__ int    d_rowptr[NN];
__device__ int    d_cursor[NN];
__device__ uint4  d_csr4[EE];            // {t, g_bits, eid, h} per CSR slot
__device__ float  d_gumcsr[EE];          // layer-1 gumbel + b2, CSR order
__device__ float  d_w[EE];               // layer-0 weights, ORIGINAL edge order
__device__ float  d_wcsr[EE];            // layer-1 weights, CSR order
__device__ int    d_agg[SCAN_BLOCKS];    // decoupled-lookback state
__device__ int    d_aggflag[SCAN_BLOCKS];
__device__ int    d_chunkdone[SCAN_BLOCKS];

__device__ __forceinline__ float fsig(float x) {
    return __fdividef(1.0f, 1.0f + __expf(-x));
}

// ---- packed f32x2 helpers --------------------------------------------------
__device__ __forceinline__ unsigned long long pack2(float x, float y) {
    unsigned long long r;
    asm("mov.b64 %0,{%1,%2};" : "=l"(r) : "f"(x), "f"(y));
    return r;
}
__device__ __forceinline__ float2 unpack2(unsigned long long v) {
    float2 r;
    asm("mov.b64 {%0,%1},%2;" : "=f"(r.x), "=f"(r.y) : "l"(v));
    return r;
}
__device__ __forceinline__ void fma2(unsigned long long& d,
                                     unsigned long long a, unsigned long long b) {
    asm("fma.rn.f32x2 %0, %1, %2, %0;" : "+l"(d) : "l"(a), "l"(b));
}

// ---- fp16 vector helpers ---------------------------------------------------
__device__ __forceinline__ void ld_h8(const __half* p, float* f) {
    uint4 r = *(const uint4*)p;
    float2 a = __half22float2(*reinterpret_cast<__half2*>(&r.x));
    float2 b = __half22float2(*reinterpret_cast<__half2*>(&r.y));
    float2 c = __half22float2(*reinterpret_cast<__half2*>(&r.z));
    float2 d = __half22float2(*reinterpret_cast<__half2*>(&r.w));
    f[0] = a.x; f[1] = a.y; f[2] = b.x; f[3] = b.y;
    f[4] = c.x; f[5] = c.y; f[6] = d.x; f[7] = d.y;
}
__device__ __forceinline__ void st_h4(__half* p, float4 v) {
    __half2 h0 = __floats2half2_rn(v.x, v.y);
    __half2 h1 = __floats2half2_rn(v.z, v.w);
    uint2 r;
    r.x = *reinterpret_cast<unsigned*>(&h0);
    r.y = *reinterpret_cast<unsigned*>(&h1);
    *(uint2*)p = r;
}
__device__ __forceinline__ void st_h8(__half* p, const float* f) {
    __half2 h0 = __floats2half2_rn(f[0], f[1]);
    __half2 h1 = __floats2half2_rn(f[2], f[3]);
    __half2 h2 = __floats2half2_rn(f[4], f[5]);
    __half2 h3 = __floats2half2_rn(f[6], f[7]);
    uint4 r;
    r.x = *reinterpret_cast<unsigned*>(&h0);
    r.y = *reinterpret_cast<unsigned*>(&h1);
    r.z = *reinterpret_cast<unsigned*>(&h2);
    r.w = *reinterpret_cast<unsigned*>(&h3);
    *(uint4*)p = r;
}
// raw uint4 (8 fp16) -> FMA into 8 fp32 accumulators, converting on the fly
__device__ __forceinline__ void fma_h8(float* acc, uint4 r, float s) {
    float2 f;
    f = __half22float2(*reinterpret_cast<__half2*>(&r.x));
    acc[0] = fmaf(s, f.x, acc[0]); acc[1] = fmaf(s, f.y, acc[1]);
    f = __half22float2(*reinterpret_cast<__half2*>(&r.y));
    acc[2] = fmaf(s, f.x, acc[2]); acc[3] = fmaf(s, f.y, acc[3]);
    f = __half22float2(*reinterpret_cast<__half2*>(&r.z));
    acc[4] = fmaf(s, f.x, acc[4]); acc[5] = fmaf(s, f.y, acc[5]);
    f = __half22float2(*reinterpret_cast<__half2*>(&r.w));
    acc[6] = fmaf(s, f.x, acc[6]); acc[7] = fmaf(s, f.y, acc[7]);
}

// ---------------------------------------------------------------------------
// L0: zero deg + lookback flags, build fp16 mirrors of emb0
// ---------------------------------------------------------------------------
__global__ void k_pre(const float4* __restrict__ emb0) {
    int i = blockIdx.x * blockDim.x + threadIdx.x;
    if (i < NN) d_deg[i] = 0;
    if (i < SCAN_BLOCKS) { d_aggflag[i] = 0; d_chunkdone[i] = 0; }
    if (i < NN * DD / 4) {
        float4 v = emb0[i];
        st_h4(&d_e0h[0][i * 4], v);
        st_h4(&d_e1h[0][i * 4], v);
    }
}

// ---------------------------------------------------------------------------
// L1 / L4: fused MLPs (+ optional degree count).
// blocks [0,296): pq      blocks [296,592): gate     blocks [592,792): count
// ---------------------------------------------------------------------------
__global__ __launch_bounds__(256) void k_mlp(
    const float* __restrict__ e1c, const float* __restrict__ e2c,
    const float* __restrict__ eW1, const float* __restrict__ eb1,  // [128,64],[64]
    const float* __restrict__ mW1, const float* __restrict__ mb1,  // [64,64],[64]
    const float* __restrict__ mW2, const float* __restrict__ mb2,  // [64,64],[64]
    const float* __restrict__ ngum,                                // [N,64]
    const int* __restrict__ h_idx)                                 // may be unused
{
    __shared__ float sW[128 * 64];   // pq: full W1. gate: [0..4095]=W1, [4096..]=W2
    __shared__ float sBa[64], sBb[64];

    int tid = threadIdx.x;
    int bid = blockIdx.x;

    if (bid >= 592) {  // count
        for (int e = (bid - 592) * 256 + tid; e < EE; e += 200 * 256)
            atomicAdd(&d_deg[h_idx[e]], 1);
        return;
    }

    int lane = tid & 31;
    int j = lane * 2;

    if (bid < 296) {
        // ---- pq: Ph = e1 @ W1_top + b1 ; Qh = e1 @ W1_bot ----
        for (int i = tid; i < 128 * 64 / 4; i += 256)
            ((float4*)sW)[i] = ((const float4*)eW1)[i];
        if (tid < 64) sBa[tid] = eb1[tid];
        __syncthreads();

        int gwarp = bid * 8 + (tid >> 5);
        int nwarps = 296 * 8;
        unsigned long long binit = *(const unsigned long long*)&sBa[j];

        for (int n0 = gwarp * 4; n0 < NN; n0 += nwarps * 4) {
            float a[4], b[4];
            unsigned long long p[4], q[4];
#pragma unroll
            for (int m = 0; m < 4; m++) {
                a[m] = e1c[(n0 + m) * 64 + lane];
                b[m] = e1c[(n0 + m) * 64 + 32 + lane];
                p[m] = binit;
                q[m] = pack2(0.0f, 0.0f);
            }
#pragma unroll
            for (int k = 0; k < 64; k++) {
                unsigned long long wt = *(const unsigned long long*)&sW[k * 64 + j];
                unsigned long long wb = *(const unsigned long long*)&sW[4096 + k * 64 + j];
#pragma unroll
                for (int m = 0; m < 4; m++) {
                    float v = __shfl_sync(0xffffffffu, (k < 32) ? a[m] : b[m], k & 31);
                    unsigned long long vv = pack2(v, v);
                    fma2(p[m], vv, wt);
                    fma2(q[m], vv, wb);
                }
            }
#pragma unroll
            for (int m = 0; m < 4; m++) {
                float2 pf = unpack2(p[m]);
                float2 qf = unpack2(q[m]);
                *(__half2*)&d_Ph[(n0 + m) * 64 + j] = __floats2half2_rn(pf.x, pf.y);
                *(__half2*)&d_Qh[(n0 + m) * 64 + j] = __floats2half2_rn(qf.x, qf.y);
            }
        }
    } else {
        // ---- gate: gatedh = sigmoid(gum + relu(e2@W1+b1)@W2 + b2) * e2 ----
        for (int i = tid; i < 64 * 64 / 4; i += 256) {
            ((float4*)sW)[i] = ((const float4*)mW1)[i];
            ((float4*)(sW + 4096))[i] = ((const float4*)mW2)[i];
        }
        if (tid < 64) { sBa[tid] = mb1[tid]; sBb[tid] = mb2[tid]; }
        __syncthreads();

        int gwarp = (bid - 296) * 8 + (tid >> 5);
        int nwarps = 296 * 8;
        unsigned long long b1init = *(const unsigned long long*)&sBa[j];
        unsigned long long b2init = *(const unsigned long long*)&sBb[j];

        for (int n0 = gwarp * 4; n0 < NN; n0 += nwarps * 4) {
            float a[4], b[4];
            unsigned long long hacc[4];
#pragma unroll
            for (int m = 0; m < 4; m++) {
                a[m] = e2c[(n0 + m) * 64 + lane];
                b[m] = e2c[(n0 + m) * 64 + 32 + lane];
                hacc[m] = b1init;
            }
#pragma unroll
            for (int k = 0; k < 64; k++) {
                unsigned long long w1 = *(const unsigned long long*)&sW[k * 64 + j];
#pragma unroll
                for (int m = 0; m < 4; m++) {
                    float v = __shfl_sync(0xffffffffu, (k < 32) ? a[m] : b[m], k & 31);
                    fma2(hacc[m], pack2(v, v), w1);
                }
            }
            float2 h[4];
            unsigned long long lg[4];
#pragma unroll
            for (int m = 0; m < 4; m++) {
                float2 hf = unpack2(hacc[m]);
                h[m] = make_float2(fmaxf(hf.x, 0.0f), fmaxf(hf.y, 0.0f));
                lg[m] = b2init;
            }
#pragma unroll
            for (int k = 0; k < 64; k++) {
                unsigned long long w2 = *(const unsigned long long*)&sW[4096 + k * 64 + j];
#pragma unroll
                for (int m = 0; m < 4; m++) {
                    float hv = __shfl_sync(0xffffffffu, (k & 1) ? h[m].y : h[m].x, k >> 1);
                    fma2(lg[m], pack2(hv, hv), w2);
                }
            }
#pragma unroll
            for (int m = 0; m < 4; m++) {
                int n = n0 + m;
                float2 lgf = unpack2(lg[m]);
                float2 gmv = *(const float2*)&ngum[n * 64 + j];
                float2 x2 = *(const float2*)&e2c[n * 64 + j];
                float gx = fsig(gmv.x + lgf.x);
                float gy = fsig(gmv.y + lgf.y);
                *(__half2*)&d_gatedh[n * 64 + j] = __floats2half2_rn(gx * x2.x, gy * x2.y);
            }
        }
    }
}

// ---------------------------------------------------------------------------
// Layer-0 edge weights, ORIGINAL edge order (overlaps CSR build in L2).
// ---------------------------------------------------------------------------
__device__ __forceinline__ void edgew_body(
    int block0, int nblocks,
    const int* __restrict__ h_idx, const int* __restrict__ t_idx,
    const float* __restrict__ gum, float b2, const float* sW2)
{
    int tid = threadIdx.x;
    int sub = tid & 7;
    int grp = tid >> 3;
    int j = sub * 8;

    for (int e = (blockIdx.x - block0) * 32 + grp; e < EE; e += nblocks * 32) {
        int h = h_idx[e];
        int t = t_idx[e];
        float p[8], q[8];
        ld_h8(&d_Ph[h * 64 + j], p);
        ld_h8(&d_Qh[t * 64 + j], q);
        float dot = 0.0f;
#pragma unroll
        for (int k = 0; k < 8; k++)
            dot = fmaf(fmaxf(p[k] + q[k], 0.0f), sW2[j + k], dot);
#pragma unroll
        for (int off = 4; off >= 1; off >>= 1)
            dot += __shfl_xor_sync(0xffffffffu, dot, off, 8);
        if (sub == 0)
            d_w[e] = fsig(gum[e] + b2 + dot);
    }
}

// ---------------------------------------------------------------------------
// L2: decoupled-lookback CSR scan + fill, overlapped with layer-0 edge weights.
// blocks [0,98): scan own 1024-node chunk, then join fill
// blocks [98,298): fill (spin on chunk-ready flags)
// blocks [298,710): edge weights (original order)
// ---------------------------------------------------------------------------
__global__ __launch_bounds__(256) void k_build_edgew(
    const int* __restrict__ h_idx, const int* __restrict__ t_idx,
    const float* __restrict__ G,
    const float* __restrict__ egum,  // [L,E] base
    const float* __restrict__ W2, const float* __restrict__ eb2)
{
    __shared__ int sScan[256];
    __shared__ int sRed[256];
    __shared__ float sW2[64];

    int tid = threadIdx.x;
    int bid = blockIdx.x;

    if (bid >= FILL_BLOCKS) {
        // ---------------- layer-0 edge weights ----------------
        if (tid < 64) sW2[tid] = W2[tid];
        __syncthreads();
        float b2 = __ldg(&eb2[0]);
        edgew_body(FILL_BLOCKS, EDGEW_BLOCKS, h_idx, t_idx, egum, b2, sW2);
        return;
    }

    if (bid < SCAN_BLOCKS) {
        // ---------------- lookback scan for chunk bid ----------------
        int nbase = bid * CHUNK + tid * 4;
        int d0 = 0, d1 = 0, d2 = 0, d3 = 0;
        if (nbase + 0 < NN) d0 = d_deg[nbase + 0];
        if (nbase + 1 < NN) d1 = d_deg[nbase + 1];
        if (nbase + 2 < NN) d2 = d_deg[nbase + 2];
        if (nbase + 3 < NN) d3 = d_deg[nbase + 3];
        int mysum = d0 + d1 + d2 + d3;
        sScan[tid] = mysum;
        __syncthreads();
        for (int off = 1; off < 256; off <<= 1) {
            int v = (tid >= off) ? sScan[tid - off] : 0;
            __syncthreads();
            sScan[tid] += v;
            __syncthreads();
        }
        int excl = sScan[tid] - mysum;
        if (tid == 255) {
            d_agg[bid] = sScan[255];
            __threadfence();
            *((volatile int*)&d_aggflag[bid]) = 1;
        }
        int pv = 0;
        if (tid < bid) {
            while (*((volatile int*)&d_aggflag[tid]) == 0) { }
            pv = d_agg[tid];
        }
        sRed[tid] = pv;
        __syncthreads();
        for (int off = 128; off >= 1; off >>= 1) {
            if (tid < off) sRed[tid] += sRed[tid + off];
            __syncthreads();
        }
        int run = sRed[0] + excl;
        if (nbase + 0 < NN) { d_rowptr[nbase + 0] = run; d_cursor[nbase + 0] = run; run += d0; }
        if (nbase + 1 < NN) { d_rowptr[nbase + 1] = run; d_cursor[nbase + 1] = run; run += d1; }
        if (nbase + 2 < NN) { d_rowptr[nbase + 2] = run; d_cursor[nbase + 2] = run; run += d2; }
        if (nbase + 3 < NN) { d_rowptr[nbase + 3] = run; d_cursor[nbase + 3] = run; run += d3; }
        __threadfence();
        __syncthreads();
        if (tid == 0) *((volatile int*)&d_chunkdone[bid]) = 1;
    }

    // ---------------- fill (all blocks [0,298), spin per chunk) ----------------
    float b2l1 = __ldg(&eb2[1]);
    for (int e = bid * 256 + tid; e < EE; e += FILL_BLOCKS * 256) {
        int h = h_idx[e];
        int c = h >> 10;
        while (*((volatile int*)&d_chunkdone[c]) == 0) { }
        int pos = atomicAdd(&d_cursor[h], 1);
        d_csr4[pos] = make_uint4((unsigned)t_idx[e], __float_as_uint(G[e]),
                                 (unsigned)e, (unsigned)h);
        d_gumcsr[pos] = egum[EE + e] + b2l1;
    }
}

// ---------------------------------------------------------------------------
// L5: layer-1 edge weights, CSR order (sequential w writes, staged gumbel)
// ---------------------------------------------------------------------------
__global__ __launch_bounds__(256) void k_edgew_csr(
    const float* __restrict__ W2)
{
    __shared__ float sW2[64];
    if (threadIdx.x < 64) sW2[threadIdx.x] = W2[threadIdx.x];
    __syncthreads();

    int tid = threadIdx.x;
    int sub = tid & 7;
    int grp = tid >> 3;
    int j = sub * 8;

    for (int pos = blockIdx.x * 32 + grp; pos < EE; pos += 1184 * 32) {
        uint4 E = d_csr4[pos];
        int t = (int)E.x;
        int h = (int)E.w;
        float p[8], q[8];
        ld_h8(&d_Ph[h * 64 + j], p);
        ld_h8(&d_Qh[t * 64 + j], q);
        float dot = 0.0f;
#pragma unroll
        for (int k = 0; k < 8; k++)
            dot = fmaf(fmaxf(p[k] + q[k], 0.0f), sW2[j + k], dot);
#pragma unroll
        for (int off = 4; off >= 1; off >>= 1)
            dot += __shfl_xor_sync(0xffffffffu, dot, off, 8);
        if (sub == 0)
            d_wcsr[pos] = fsig(d_gumcsr[pos] + dot);
    }
}

// ---------------------------------------------------------------------------
// L3/L6: per-node 3-branch SpMM + row norm + residual.  8 threads/node.
// 2-edge software pipeline; features staged raw (uint4) and converted at FMA.
// wmode=0: w = warr[E.z] (original order).  wmode=1: w = warr[pos] (CSR order).
// last=0: write fp32 state + fp16 mirrors.   last=1: out = emb0 + c + o.
// ---------------------------------------------------------------------------
__global__ __launch_bounds__(256) void k_gather(
    const float* __restrict__ e0c, const float* __restrict__ e1c,
    const float* __restrict__ e2c,
    const __half* __restrict__ e0h, const __half* __restrict__ e1h,
    float* __restrict__ e0n, float* __restrict__ e1n, float* __restrict__ e2n,
    __half* __restrict__ e0nh, __half* __restrict__ e1nh,
    const float* __restrict__ emb0, float* __restrict__ out,
    const float* __restrict__ warr, int wmode, int last)
{
    int node = blockIdx.x * 32 + (threadIdx.x >> 3);  // 3125 * 32 = 100000
    int sub = threadIdx.x & 7;
    int j = sub * 8;

    int p = d_rowptr[node];
    int rem = d_deg[node];

    float rowsum = 0.0f;
    float a0[8], a1[8], a2[8];
#pragma unroll
    for (int k = 0; k < 8; k++) { a0[k] = 0.f; a1[k] = 0.f; a2[k] = 0.f; }

    // odd leading edge
    if (rem & 1) {
        uint4 E = d_csr4[p];
        float w = wmode ? warr[p] : warr[E.z];
        float g = __uint_as_float(E.y);
        int t = (int)E.x;
        uint4 r0 = *(const uint4*)&e0h[t * 64 + j];
        uint4 r1 = *(const uint4*)&e1h[t * 64 + j];
        uint4 r2 = *(const uint4*)&d_gatedh[t * 64 + j];
        rowsum += w;
        fma_h8(a0, r0, g);
        fma_h8(a1, r1, w);
        fma_h8(a2, r2, g);
        p++; rem--;
    }

    if (rem > 0) {
        // preload first pair
        uint4 Ea = d_csr4[p];
        uint4 Eb = d_csr4[p + 1];
        float wa = wmode ? warr[p] : warr[Ea.z];
        float wb = wmode ? warr[p + 1] : warr[Eb.z];

        for (int it = 0; it < rem; it += 2) {
            uint4 Ca = Ea, Cb = Eb;
            float cwa = wa, cwb = wb;
            if (it + 3 < rem) {
                int np = p + it + 2;
                Ea = d_csr4[np];
                Eb = d_csr4[np + 1];
                wa = wmode ? warr[np] : warr[Ea.z];
                wb = wmode ? warr[np + 1] : warr[Eb.z];
            }
            int ta = (int)Ca.x, tb = (int)Cb.x;
            float ga = __uint_as_float(Ca.y), gb = __uint_as_float(Cb.y);
            // issue all six independent 16B feature loads
            uint4 r0a = *(const uint4*)&e0h[ta * 64 + j];
            uint4 r1a = *(const uint4*)&e1h[ta * 64 + j];
            uint4 r2a = *(const uint4*)&d_gatedh[ta * 64 + j];
            uint4 r0b = *(const uint4*)&e0h[tb * 64 + j];
            uint4 r1b = *(const uint4*)&e1h[tb * 64 + j];
            uint4 r2b = *(const uint4*)&d_gatedh[tb * 64 + j];
            rowsum += cwa + cwb;
            fma_h8(a0, r0a, ga);
            fma_h8(a1, r1a, cwa);
            fma_h8(a2, r2a, ga);
            fma_h8(a0, r0b, gb);
            fma_h8(a1, r1b, cwb);
            fma_h8(a2, r2b, gb);
        }
    }

    float dinv = (rowsum > 0.0f) ? (1.0f / rowsum) : 0.0f;

    float c0[8], c1[8], c2[8], o0[8], o1[8], o2[8];
    *(float4*)&c0[0] = *(const float4*)&e0c[node * 64 + j];
    *(float4*)&c0[4] = *(const float4*)&e0c[node * 64 + j + 4];
    *(float4*)&c1[0] = *(const float4*)&e1c[node * 64 + j];
    *(float4*)&c1[4] = *(const float4*)&e1c[node * 64 + j + 4];
    *(float4*)&c2[0] = *(const float4*)&e2c[node * 64 + j];
    *(float4*)&c2[4] = *(const float4*)&e2c[node * 64 + j + 4];
#pragma unroll
    for (int k = 0; k < 8; k++) {
        o0[k] = c0[k] + a0[k];
        o1[k] = fmaf(dinv, a1[k], c1[k]);
        o2[k] = c2[k] + a2[k];
    }

    if (!last) {
        *(float4*)&e0n[node * 64 + j]     = *(float4*)&o0[0];
        *(float4*)&e0n[node * 64 + j + 4] = *(float4*)&o0[4];
        *(float4*)&e1n[node * 64 + j]     = *(float4*)&o1[0];
        *(float4*)&e1n[node * 64 + j + 4] = *(float4*)&o1[4];
        *(float4*)&e2n[node * 64 + j]     = *(float4*)&o2[0];
        *(float4*)&e2n[node * 64 + j + 4] = *(float4*)&o2[4];
        st_h8(&e0nh[node * 64 + j], o0);
        st_h8(&e1nh[node * 64 + j], o1);
    } else {
        float z[8];
        *(float4*)&z[0] = *(const float4*)&emb0[node * 64 + j];
        *(float4*)&z[4] = *(const float4*)&emb0[node * 64 + j + 4];
        const int per = NN * DD;
        float r[8];
#pragma unroll
        for (int k = 0; k < 8; k++) r[k] = z[k] + c0[k] + o0[k];
        *(float4*)&out[0 * per + node * 64 + j]     = *(float4*)&r[0];
        *(float4*)&out[0 * per + node * 64 + j + 4] = *(float4*)&r[4];
#pragma unroll
        for (int k = 0; k < 8; k++) r[k] = z[k] + c1[k] + o1[k];
        *(float4*)&out[1 * per + node * 64 + j]     = *(float4*)&r[0];
        *(float4*)&out[1 * per + node * 64 + j + 4] = *(float4*)&r[4];
#pragma unroll
        for (int k = 0; k < 8; k++) r[k] = z[k] + c2[k] + o2[k];
        *(float4*)&out[2 * per + node * 64 + j]     = *(float4*)&r[0];
        *(float4*)&out[2 * per + node * 64 + j + 4] = *(float4*)&r[4];
    }
}

// ---------------------------------------------------------------------------
// Host launcher (graph-capturable: launches only)
// ---------------------------------------------------------------------------
extern "C" void kernel_launch(void* const* d_in, const int* in_sizes, int n_in,
                              void* d_out, int out_size) {
    const float* emb0 = (const float*)d_in[0];
    const int*   hI   = (const int*)  d_in[1];
    const int*   tI   = (const int*)  d_in[2];
    const float* G    = (const float*)d_in[3];
    const float* egum = (const float*)d_in[4];   // [L,E]
    const float* ngum = (const float*)d_in[5];   // [L,N,D]
    const float* eW1  = (const float*)d_in[6];   // [L,128,64]
    const float* eb1  = (const float*)d_in[7];   // [L,64]
    const float* eW2  = (const float*)d_in[8];   // [L,64,1]
    const float* eb2  = (const float*)d_in[9];   // [L,1]
    const float* mW1  = (const float*)d_in[10];  // [L,64,64]
    const float* mb1  = (const float*)d_in[11];  // [L,64]
    const float* mW2  = (const float*)d_in[12];  // [L,64,64]
    const float* mb2  = (const float*)d_in[13];  // [L,64]
    float* out = (float*)d_out;

    float* base;
    cudaGetSymbolAddress((void**)&base, d_eb);
    __half* h0base;
    cudaGetSymbolAddress((void**)&h0base, d_e0h);
    __half* h1base;
    cudaGetSymbolAddress((void**)&h1base, d_e1h);
    float* wbase;
    cudaGetSymbolAddress((void**)&wbase, d_w);
    float* wcsrbase;
    cudaGetSymbolAddress((void**)&wcsrbase, d_wcsr);

    float* ebuf[3];
    for (int b = 0; b < 3; b++)
        ebuf[b] = base + (size_t)b * NN * DD;
    __half* e0hbuf[2] = { h0base, h0base + (size_t)NN * DD };
    __half* e1hbuf[2] = { h1base, h1base + (size_t)NN * DD };

    // L0: zero + mirrors + flags
    k_pre<<<(NN * DD / 4 + 255) / 256, 256>>>((const float4*)emb0);

    // L1: layer-0 MLPs + degree count
    k_mlp<<<792, 256>>>(emb0, emb0, eW1, eb1, mW1, mb1, mW2, mb2, ngum, hI);

    // L2: CSR scan+fill overlapped with layer-0 edge weights
    k_build_edgew<<<L2_GRID, 256>>>(hI, tI, G, egum, eW2, eb2);

    // L3: layer-0 gather  <-- profiled launch (index 3)
    k_gather<<<3125, 256>>>(emb0, emb0, emb0, e0hbuf[0], e1hbuf[0],
                            ebuf[0], ebuf[1], ebuf[2],
                            e0hbuf[1], e1hbuf[1],
                            emb0, out, wbase, 0, 0);

    // L4: layer-1 MLPs
    k_mlp<<<592, 256>>>(ebuf[1], ebuf[2],
                        eW1 + 128 * 64, eb1 + 64,
                        mW1 + 64 * 64, mb1 + 64, mW2 + 64 * 64, mb2 + 64,
                        ngum + (size_t)NN * 64, hI);

    // L5: layer-1 edge weights (CSR order)
    k_edgew_csr<<<1184, 256>>>(eW2 + 64);

    // L6: layer-1 gather + final output
    k_gather<<<3125, 256>>>(ebuf[0], ebuf[1], ebuf[2], e0hbuf[1], e1hbuf[1],
                            ebuf[0], ebuf[1], ebuf[2],
                            e0hbuf[0], e1hbuf[0],
                            emb0, out, wcsrbase, 1, 1);
}